// round 14
// baseline (speedup 1.0000x reference)
#include <cuda_runtime.h>
#include <cuda_bf16.h>
#include <cstdint>
#include <math.h>

// ---------------- scratch ---------------------------------------------------
__device__ uint32_t g_kb[128u * 2048u * 32u];   // k bf16 [B][N][64]
__device__ uint32_t g_vb[128u * 2048u * 32u];   // v bf16
__device__ float4   g_q4[128u * 8u * 16u];      // q fp32 [B,S,64]
__device__ float    g_slots[128 * 8 * 64];
__device__ float    g_csP[8 * 128 * 8];
__device__ float    g_updp[8 * 128 * 8 * 64];
__device__ uint32_t g_cwb[2][8192];             // conv W bf16 [64][256]/2
__device__ uint32_t g_wkb[2048], g_wvb[2048];   // Wk/Wv bf16 [64][64]/2
__device__ float    g_wihT[12288];              // [c][192]
__device__ float    g_whhT[12288];              // [c][192]
__device__ float    g_w1T[8192];                // [c][128]
__device__ float    g_w2T[8192];                // [j][64]

// ---------------- helpers ---------------------------------------------------
__device__ __forceinline__ void mma16816(float* c, const uint32_t* a,
                                         uint32_t b0, uint32_t b1) {
    asm volatile(
        "mma.sync.aligned.m16n8k16.row.col.f32.bf16.bf16.f32 "
        "{%0,%1,%2,%3}, {%4,%5,%6,%7}, {%8,%9}, {%0,%1,%2,%3};"
        : "+f"(c[0]), "+f"(c[1]), "+f"(c[2]), "+f"(c[3])
        : "r"(a[0]), "r"(a[1]), "r"(a[2]), "r"(a[3]), "r"(b0), "r"(b1));
}
__device__ __forceinline__ void ldsm_x4(uint32_t* r, uint32_t addr) {
    asm volatile("ldmatrix.sync.aligned.m8n8.x4.shared.b16 {%0,%1,%2,%3}, [%4];"
                 : "=r"(r[0]), "=r"(r[1]), "=r"(r[2]), "=r"(r[3]) : "r"(addr));
}
__device__ __forceinline__ void ldsm_x4_t(uint32_t* r, uint32_t addr) {
    asm volatile("ldmatrix.sync.aligned.m8n8.x4.trans.shared.b16 {%0,%1,%2,%3}, [%4];"
                 : "=r"(r[0]), "=r"(r[1]), "=r"(r[2]), "=r"(r[3]) : "r"(addr));
}
__device__ __forceinline__ uint32_t smem_u32(const void* p) {
    uint32_t a;
    asm("{ .reg .u64 t; cvta.to.shared.u64 t, %1; cvt.u32.u64 %0, t; }"
        : "=r"(a) : "l"(p));
    return a;
}
__device__ __forceinline__ uint32_t pack2(float a, float b) {
    __nv_bfloat162 h;
    h.x = __float2bfloat16_rn(a);
    h.y = __float2bfloat16_rn(b);
    return *(uint32_t*)&h;
}
__device__ __forceinline__ float2 bf2f(uint32_t u) {
    return __bfloat1622float2(*(__nv_bfloat162*)&u);
}

// conv smem layout
#define SX 136
#define SKD 72
#define OFF_XB0  0u
#define OFF_XB1  17408u
#define OFF_WB0  34816u
#define OFF_WB1  44032u
#define OFF_WK   53248u
#define OFF_WV   62464u
#define SM_TOTAL 71680u
#define OFF_YS    0u
#define OFF_A2    34816u
#define OFF_STAGE 0u

// ===========================================================================
// Kernel 0a: init slots
// ===========================================================================
__global__ void init_slots_kernel(const float* __restrict__ mu,
                                  const float* __restrict__ ls,
                                  const float* __restrict__ noise)
{
    int i = blockIdx.x * 256 + threadIdx.x;
    int d = i & 63;
    g_slots[i] = mu[d] + expf(ls[d]) * noise[i];
}

// ===========================================================================
// Kernel 0b: weight prep
// ===========================================================================
__global__ void wprep_kernel(const float* __restrict__ cw1,
                             const float* __restrict__ cw2,
                             const float* __restrict__ Wk,
                             const float* __restrict__ Wv,
                             const float* __restrict__ wih,
                             const float* __restrict__ whh,
                             const float* __restrict__ w1,
                             const float* __restrict__ w2)
{
    int i = blockIdx.x * 256 + threadIdx.x;
    if (i < 8192) {
        g_cwb[0][i] = pack2(cw1[2 * i], cw1[2 * i + 1]);
    } else if (i < 16384) {
        int j = i - 8192;
        g_cwb[1][j] = pack2(cw2[2 * j], cw2[2 * j + 1]);
    } else if (i < 18432) {
        int j = i - 16384;
        g_wkb[j] = pack2(Wk[2 * j], Wk[2 * j + 1]);
    } else if (i < 20480) {
        int j = i - 18432;
        g_wvb[j] = pack2(Wv[2 * j], Wv[2 * j + 1]);
    } else if (i < 32768) {
        int j = i - 20480;
        int c = j / 192, row = j % 192;
        g_wihT[j] = wih[row * 64 + c];
    } else if (i < 45056) {
        int j = i - 32768;
        int c = j / 192, row = j % 192;
        g_whhT[j] = whh[row * 64 + c];
    } else if (i < 53248) {
        int j = i - 45056;
        int c = j / 128, col = j % 128;
        g_w1T[j] = w1[col * 64 + c];
    } else if (i < 61440) {
        int j3 = i - 53248;
        int j = j3 / 64, d = j3 % 64;
        g_w2T[j3] = w2[d * 128 + j];
    }
}

// ===========================================================================
// Kernel slot_q (initial q only). grid B, block 512
// ===========================================================================
__global__ void slot_q_kernel(const float* __restrict__ ns_w,
                              const float* __restrict__ ns_b,
                              const float* __restrict__ Wq)
{
    __shared__ float sn[8][64];
    __shared__ float Wqt[64][65];
    __shared__ float wsum[16], wsq[16];
    const int b = blockIdx.x;
    const int tid = threadIdx.x;
    const int s = tid >> 6, d = tid & 63;

#pragma unroll
    for (int j = 0; j < 8; ++j) {
        int lin = j * 512 + tid;
        int e = lin >> 6, c = lin & 63;
        Wqt[c][e] = Wq[lin];
    }
    float v = g_slots[(b * 8 + s) * 64 + d];
    float su = v, sq = v * v;
#pragma unroll
    for (int o = 16; o > 0; o >>= 1) {
        su += __shfl_xor_sync(0xffffffffu, su, o);
        sq += __shfl_xor_sync(0xffffffffu, sq, o);
    }
    if ((tid & 31) == 0) { wsum[tid >> 5] = su; wsq[tid >> 5] = sq; }
    __syncthreads();
    float ts = wsum[s * 2] + wsum[s * 2 + 1];
    float tq = wsq[s * 2] + wsq[s * 2 + 1];
    float mu = ts * (1.f / 64.f);
    float inv = rsqrtf(tq * (1.f / 64.f) - mu * mu + 1e-5f);
    sn[s][d] = (v - mu) * inv * ns_w[d] + ns_b[d];
    __syncthreads();
    float acc = 0.f;
#pragma unroll
    for (int c = 0; c < 64; ++c) acc += sn[s][c] * Wqt[c][d];
    ((float*)g_q4)[(b * 8 + s) * 64 + d] = acc * 0.125f;
}

// ===========================================================================
// Kernel 1 (profiled slot): conv (pipelined) -> LN -> LN -> k,v GEMMs
// ===========================================================================
__global__ __launch_bounds__(256)
void conv_ln_kv_kernel(
    const float* __restrict__ x1, const float* __restrict__ x2,
    const float* __restrict__ cb1, const float* __restrict__ cb2,
    const float* __restrict__ norm_w, const float* __restrict__ norm_b,
    const float* __restrict__ ni_w,  const float* __restrict__ ni_b)
{
    extern __shared__ char smem[];
    const uint32_t sb = smem_u32(smem);
    const int tid = threadIdx.x;
    const int w = tid >> 5, lane = tid & 31;
    const int g = lane >> 2, tg = lane & 3;
    const int rowin = lane & 7, quad = lane >> 3;
    const int M0 = (w & 3) * 16;
    const int N0 = (w >> 2) * 64;
    const int b = blockIdx.z, src = blockIdx.y;
    const int p0 = blockIdx.x * 128;

    const float* X    = (src ? x2 : x1) + (size_t)b * 262144 + p0;
    const float* bias = src ? cb2 : cb1;
    const uint4* Wsrc = (const uint4*)(g_cwb[src]);

    const uint32_t laneW  = (uint32_t)(((M0 + rowin + (quad & 1) * 8) * SKD
                                        + (quad >> 1) * 8) * 2);
    const uint32_t laneBX = (uint32_t)(((rowin + (quad & 1) * 8) * SX
                                        + N0 + (quad >> 1) * 8) * 2);
    const uint32_t laneB2 = (uint32_t)(((rowin + (quad >> 1) * 8) * SKD
                                        + (quad & 1) * 8) * 2);

#pragma unroll
    for (int it = 0; it < 2; ++it) {
        int idx = it * 256 + tid;
        int e = idx >> 3, q = idx & 7;
        *(uint4*)(smem + OFF_WK + (uint32_t)(e * 144 + q * 16)) =
            ((const uint4*)g_wkb)[e * 8 + q];
        *(uint4*)(smem + OFF_WV + (uint32_t)(e * 144 + q * 16)) =
            ((const uint4*)g_wvb)[e * 8 + q];
    }

    // prologue: chunk 0 -> buf0
#pragma unroll
    for (int it = 0; it < 8; ++it) {
        int idx = it * 256 + tid;
        int ch = idx >> 5, p4 = idx & 31;
        float4 x4 = *(const float4*)(X + (size_t)ch * 1024 + p4 * 4);
        uint2 pr;
        pr.x = pack2(x4.x, x4.y);
        pr.y = pack2(x4.z, x4.w);
        *(uint2*)(smem + OFF_XB0 + (uint32_t)((ch * SX + p4 * 4) * 2)) = pr;
    }
#pragma unroll
    for (int it = 0; it < 2; ++it) {
        int idx = it * 256 + tid;
        int d = idx >> 3, q = idx & 7;
        *(uint4*)(smem + OFF_WB0 + (uint32_t)(d * 144 + q * 16)) =
            Wsrc[d * 32 + q];
    }
    __syncthreads();

    float acc[8][4];
#pragma unroll
    for (int nf = 0; nf < 8; ++nf)
#pragma unroll
        for (int i = 0; i < 4; ++i) acc[nf][i] = 0.f;

    const uint32_t xoff[2] = {OFF_XB0, OFF_XB1};
    const uint32_t woff[2] = {OFF_WB0, OFF_WB1};

#pragma unroll
    for (int chunk = 0; chunk < 4; ++chunk) {
        const int cur = chunk & 1;
        float4 xv[8];
        uint4 wv[2];
        if (chunk < 3) {
            const int cb = (chunk + 1) * 64;
#pragma unroll
            for (int it = 0; it < 8; ++it) {
                int idx = it * 256 + tid;
                int ch = idx >> 5, p4 = idx & 31;
                xv[it] = *(const float4*)(X + (size_t)(cb + ch) * 1024 + p4 * 4);
            }
#pragma unroll
            for (int it = 0; it < 2; ++it) {
                int idx = it * 256 + tid;
                int d = idx >> 3, q = idx & 7;
                wv[it] = Wsrc[d * 32 + (chunk + 1) * 8 + q];
            }
        }
        const uint32_t xb = sb + xoff[cur];
        const uint32_t wb = sb + woff[cur];
#pragma unroll
        for (int ks = 0; ks < 4; ++ks) {
            uint32_t ah[4], bx[4];
            ldsm_x4(ah, wb + laneW + ks * 32);
#pragma unroll
            for (int nfp = 0; nfp < 4; ++nfp) {
                ldsm_x4_t(bx, xb + laneBX
                              + (uint32_t)(ks * 16 * SX * 2) + nfp * 32);
                mma16816(acc[2 * nfp],     ah, bx[0], bx[1]);
                mma16816(acc[2 * nfp + 1], ah, bx[2], bx[3]);
            }
        }
        if (chunk < 3) {
            const int nxt = cur ^ 1;
#pragma unroll
            for (int it = 0; it < 8; ++it) {
                int idx = it * 256 + tid;
                int ch = idx >> 5, p4 = idx & 31;
                uint2 pr;
                pr.x = pack2(xv[it].x, xv[it].y);
                pr.y = pack2(xv[it].z, xv[it].w);
                *(uint2*)(smem + xoff[nxt] +
                          (uint32_t)((ch * SX + p4 * 4) * 2)) = pr;
            }
#pragma unroll
            for (int it = 0; it < 2; ++it) {
                int idx = it * 256 + tid;
                int d = idx >> 3, q = idx & 7;
                *(uint4*)(smem + woff[nxt] + (uint32_t)(d * 144 + q * 16)) =
                    wv[it];
            }
        }
        __syncthreads();
    }

    float* Ys = (float*)(smem + OFF_YS);
    {
        float b0 = bias[M0 + g], b8 = bias[M0 + g + 8];
#pragma unroll
        for (int nf = 0; nf < 8; ++nf) {
            int p = N0 + nf * 8 + 2 * tg;
            Ys[p * 65 + M0 + g]           = acc[nf][0] + b0;
            Ys[(p + 1) * 65 + M0 + g]     = acc[nf][1] + b0;
            Ys[p * 65 + M0 + g + 8]       = acc[nf][2] + b8;
            Ys[(p + 1) * 65 + M0 + g + 8] = acc[nf][3] + b8;
        }
    }
    __syncthreads();

    if (tid < 128) {
        float* row = Ys + tid * 65;
        float s = 0.f, q = 0.f;
#pragma unroll
        for (int d = 0; d < 64; ++d) { float v = row[d]; s += v; q += v * v; }
        float mu = s * (1.f / 64.f);
        float inv = rsqrtf(q * (1.f / 64.f) - mu * mu + 1e-5f);
        s = 0.f; q = 0.f;
#pragma unroll
        for (int d = 0; d < 64; ++d) {
            float y = (row[d] - mu) * inv * norm_w[d] + norm_b[d];
            row[d] = y; s += y; q += y * y;
        }
        mu = s * (1.f / 64.f);
        inv = rsqrtf(q * (1.f / 64.f) - mu * mu + 1e-5f);
#pragma unroll
        for (int d = 0; d < 64; ++d)
            row[d] = (row[d] - mu) * inv * ni_w[d] + ni_b[d];
    }
    __syncthreads();

#pragma unroll
    for (int it = 0; it < 16; ++it) {
        int idx = it * 256 + tid;
        int p = idx >> 5, d2 = idx & 31;
        *(uint32_t*)(smem + OFF_A2 + (uint32_t)((p * SKD + 2 * d2) * 2)) =
            pack2(Ys[p * 65 + 2 * d2], Ys[p * 65 + 2 * d2 + 1]);
    }
    __syncthreads();

    uint32_t* kb = g_kb + (size_t)(b * 2048 + src * 1024 + p0) * 32;
    uint32_t* vb = g_vb + (size_t)(b * 2048 + src * 1024 + p0) * 32;
    float* stage = (float*)(smem + OFF_STAGE);

#pragma unroll
    for (int mat = 0; mat < 2; ++mat) {
        uint32_t Bbase = sb + (mat ? OFF_WV : OFF_WK);
        uint32_t* outb = mat ? vb : kb;
        float ac[8][4];
#pragma unroll
        for (int nf = 0; nf < 8; ++nf)
#pragma unroll
            for (int i = 0; i < 4; ++i) ac[nf][i] = 0.f;
#pragma unroll
        for (int ks = 0; ks < 4; ++ks) {
            uint32_t ah[4], bx[4];
            ldsm_x4(ah, Bbase + laneW + ks * 32);
#pragma unroll
            for (int nfp = 0; nfp < 4; ++nfp) {
                ldsm_x4(bx, sb + OFF_A2 + laneB2
                            + (uint32_t)((N0 + nfp * 16) * SKD * 2) + ks * 32);
                mma16816(ac[2 * nfp],     ah, bx[0], bx[1]);
                mma16816(ac[2 * nfp + 1], ah, bx[2], bx[3]);
            }
        }
#pragma unroll
        for (int nf = 0; nf < 8; ++nf) {
            int p = N0 + nf * 8 + 2 * tg;
            int e = M0 + g;
            stage[p * 64 + e]           = ac[nf][0];
            stage[(p + 1) * 64 + e]     = ac[nf][1];
            stage[p * 64 + e + 8]       = ac[nf][2];
            stage[(p + 1) * 64 + e + 8] = ac[nf][3];
        }
        __syncthreads();
#pragma unroll
        for (int j = 0; j < 16; ++j) {
            int idx = j * 256 + tid;
            float2 f = ((const float2*)stage)[idx];
            outb[idx] = pack2(f.x, f.y);
        }
        __syncthreads();
    }
}

// ===========================================================================
// attn_update (R11-style: direct gmem k reads, static smem). grid (8,B), 256
// ===========================================================================
__global__ void attn_update_kernel()
{
    __shared__ float qs[8][64];
    __shared__ float csw[8][8];
    __shared__ float attn_s[256][8];
    __shared__ float4 red[16][128];
    const int sp = blockIdx.x, b = blockIdx.y;
    const int tid = threadIdx.x;
    const int w = tid >> 5, lane = tid & 31;
    const int t = sp * 256 + tid;

    ((float*)qs)[tid]       = ((const float*)g_q4)[b * 512 + tid];
    ((float*)qs)[tid + 256] = ((const float*)g_q4)[b * 512 + tid + 256];
    __syncthreads();

    const uint4* kr = (const uint4*)(g_kb + ((size_t)b * 2048 + t) * 32);
    float a[8];
#pragma unroll
    for (int s = 0; s < 8; ++s) a[s] = 0.f;
#pragma unroll
    for (int i = 0; i < 8; ++i) {
        uint4 A = kr[i];
        float2 f0 = bf2f(A.x), f1 = bf2f(A.y), f2 = bf2f(A.z), f3 = bf2f(A.w);
#pragma unroll
        for (int s = 0; s < 8; ++s) {
            const float* q8 = &qs[s][8 * i];
            a[s] = fmaf(f0.x, q8[0], fmaf(f0.y, q8[1],
                   fmaf(f1.x, q8[2], fmaf(f1.y, q8[3],
                   fmaf(f2.x, q8[4], fmaf(f2.y, q8[5],
                   fmaf(f3.x, q8[6], fmaf(f3.y, q8[7], a[s]))))))));
        }
    }
    float mx = a[0];
#pragma unroll
    for (int s = 1; s < 8; ++s) mx = fmaxf(mx, a[s]);
    float sm = 0.f;
#pragma unroll
    for (int s = 0; s < 8; ++s) { a[s] = __expf(a[s] - mx); sm += a[s]; }
    float rv = 1.f / sm;
#pragma unroll
    for (int s = 0; s < 8; ++s) a[s] = a[s] * rv + 1e-8f;

    *(float4*)&attn_s[tid][0] = make_float4(a[0], a[1], a[2], a[3]);
    *(float4*)&attn_s[tid][4] = make_float4(a[4], a[5], a[6], a[7]);

#pragma unroll
    for (int s = 0; s < 8; ++s) {
        float v = a[s];
#pragma unroll
        for (int o = 16; o > 0; o >>= 1) v += __shfl_xor_sync(0xffffffffu, v, o);
        if (lane == 0) csw[w][s] = v;
    }
    __syncthreads();
    if (tid < 8) {
        float tt = 0.f;
#pragma unroll
        for (int ww = 0; ww < 8; ++ww) tt += csw[ww][tid];
        g_csP[sp * 1024 + b * 8 + tid] = tt;
    }

    const int dq = tid & 15, grp = tid >> 4;
    const uint2* V2 = (const uint2*)(g_vb + ((size_t)b * 2048 + sp * 256) * 32);
    float4 acc[8];
#pragma unroll
    for (int s = 0; s < 8; ++s) acc[s] = make_float4(0.f, 0.f, 0.f, 0.f);
#pragma unroll 4
    for (int j = 0; j < 16; ++j) {
        int tt = grp * 16 + j;
        uint2 vv = V2[tt * 16 + dq];
        float2 v01 = bf2f(vv.x), v23 = bf2f(vv.y);
        float4 A01 = *(const float4*)&attn_s[tt][0];
        float4 A23 = *(const float4*)&attn_s[tt][4];
        const float aw[8] = {A01.x, A01.y, A01.z, A01.w,
                             A23.x, A23.y, A23.z, A23.w};
#pragma unroll
        for (int s = 0; s < 8; ++s) {
            acc[s].x = fmaf(aw[s], v01.x, acc[s].x);
            acc[s].y = fmaf(aw[s], v01.y, acc[s].y);
            acc[s].z = fmaf(aw[s], v23.x, acc[s].z);
            acc[s].w = fmaf(aw[s], v23.y, acc[s].w);
        }
    }
#pragma unroll
    for (int s = 0; s < 8; ++s) red[grp][s * 16 + dq] = acc[s];
    __syncthreads();
    if (tid < 128) {
        float4 r = make_float4(0.f, 0.f, 0.f, 0.f);
#pragma unroll
        for (int q = 0; q < 16; ++q) {
            float4 tt = red[q][tid];
            r.x += tt.x; r.y += tt.y; r.z += tt.z; r.w += tt.w;
        }
        ((float4*)g_updp)[sp * 16384 + b * 128 + tid] = r;
    }
}

// ===========================================================================
// gru_mlp + fused next-iteration q. grid 128, block 512 (8 slots/block).
// ===========================================================================
__global__ void gru_mlp_kernel(
    const float* __restrict__ bih, const float* __restrict__ bhh,
    const float* __restrict__ nm_w, const float* __restrict__ nm_b,
    const float* __restrict__ b1, const float* __restrict__ b2,
    const float* __restrict__ ns_w, const float* __restrict__ ns_b,
    const float* __restrict__ Wq, int do_q)
{
    const int tid = threadIdx.x;
    const int ls = tid >> 6, d = tid & 63;
    const int bs = blockIdx.x * 8 + ls;
    __shared__ float u[8][64], sp_s[8][64], h[8][64], hh[8][128], r4[8][4];
    __shared__ float Wqt[64][65];

    float uacc = 0.f;
#pragma unroll
    for (int p = 0; p < 8; ++p) uacc += g_updp[p * 65536 + bs * 64 + d];
    float cs = 0.f;
#pragma unroll
    for (int p = 0; p < 8; ++p) cs += g_csP[p * 1024 + bs];
    u[ls][d]  = uacc / cs;
    sp_s[ls][d] = g_slots[bs * 64 + d];
    if (do_q) {
#pragma unroll
        for (int j = 0; j < 8; ++j) {
            int lin = j * 512 + tid;
            Wqt[lin & 63][lin >> 6] = Wq[lin];
        }
    }
    __syncthreads();

    float a0 = bih[d], a1 = bih[64 + d], a2 = bih[128 + d];
    float g0 = bhh[d], g1 = bhh[64 + d], g2 = bhh[128 + d];
#pragma unroll 8
    for (int c = 0; c < 64; ++c) {
        float uc = u[ls][c], sc = sp_s[ls][c];
        const float* wi = g_wihT + c * 192;
        const float* wh = g_whhT + c * 192;
        a0 = fmaf(uc, wi[d], a0);
        a1 = fmaf(uc, wi[64 + d], a1);
        a2 = fmaf(uc, wi[128 + d], a2);
        g0 = fmaf(sc, wh[d], g0);
        g1 = fmaf(sc, wh[64 + d], g1);
        g2 = fmaf(sc, wh[128 + d], g2);
    }
    float r = 1.f / (1.f + __expf(-(a0 + g0)));
    float z = 1.f / (1.f + __expf(-(a1 + g1)));
    float nn = tanhf(a2 + r * g2);
    float sl = (1.f - z) * nn + z * sp_s[ls][d];

    float su = sl, sq = sl * sl;
#pragma unroll
    for (int o = 16; o > 0; o >>= 1) {
        su += __shfl_xor_sync(0xffffffffu, su, o);
        sq += __shfl_xor_sync(0xffffffffu, sq, o);
    }
    if ((d & 31) == 0) { r4[ls][d >> 5] = su; r4[ls][2 + (d >> 5)] = sq; }
    __syncthreads();
    float ts = r4[ls][0] + r4[ls][1], tq = r4[ls][2] + r4[ls][3];
    float mu = ts * (1.f / 64.f);
    float inv = rsqrtf(tq * (1.f / 64.f) - mu * mu + 1e-5f);
    h[ls][d] = (sl - mu) * inv * nm_w[d] + nm_b[d];
    __syncthreads();

    float m0 = b1[d], m1 = b1[64 + d];
#pragma unroll 8
    for (int c = 0; c < 64; ++c) {
        float hc = h[ls][c];
        const float* w1r = g_w1T + c * 128;
        m0 = fmaf(hc, w1r[d], m0);
        m1 = fmaf(hc, w1r[64 + d], m1);
    }
    hh[ls][d] = fmaxf(m0, 0.f);
    hh[ls][64 + d] = fmaxf(m1, 0.f);
    __syncthreads();

    float o = b2[d];
#pragma unroll 8
    for (int j = 0; j < 128; ++j)
        o = fmaf(hh[ls][j], g_w2T[j * 64 + d], o);
    float newslot = sl + o;
    g_slots[bs * 64 + d] = newslot;

    if (do_q) {
        __syncthreads();
        float su2 = newslot, sq2 = newslot * newslot;
#pragma unroll
        for (int o2 = 16; o2 > 0; o2 >>= 1) {
            su2 += __shfl_xor_sync(0xffffffffu, su2, o2);
            sq2 += __shfl_xor_sync(0xffffffffu, sq2, o2);
        }
        if ((d & 31) == 0) { r4[ls][d >> 5] = su2; r4[ls][2 + (d >> 5)] = sq2; }
        __syncthreads();
        float ts2 = r4[ls][0] + r4[ls][1], tq2 = r4[ls][2] + r4[ls][3];
        float mu2 = ts2 * (1.f / 64.f);
        float inv2 = rsqrtf(tq2 * (1.f / 64.f) - mu2 * mu2 + 1e-5f);
        u[ls][d] = (newslot - mu2) * inv2 * ns_w[d] + ns_b[d];
        __syncthreads();
        float acc = 0.f;
#pragma unroll
        for (int c = 0; c < 64; ++c) acc += u[ls][c] * Wqt[c][d];
        ((float*)g_q4)[bs * 64 + d] = acc * 0.125f;
    }
}

// ===========================================================================
// Kernel 7: head
// ===========================================================================
__global__ void head_kernel(const float* __restrict__ head_w,
                            const float* __restrict__ head_b,
                            float* __restrict__ out)
{
    const int b = blockIdx.x;
    const int d = threadIdx.x;
    __shared__ float f[64];
    float a = 0.f;
#pragma unroll
    for (int s = 0; s < 8; ++s) a += g_slots[(b * 8 + s) * 64 + d];
    f[d] = a * 0.125f;
    __syncthreads();
    if (d < 15) {
        float o = head_b[d];
        const float* hw = head_w + d * 64;
#pragma unroll
        for (int c = 0; c < 64; ++c) o += f[c] * hw[c];
        out[b * 15 + d] = o;
    }
}

// ===========================================================================
extern "C" void kernel_launch(void* const* d_in, const int* in_sizes, int n_in,
                              void* d_out, int out_size)
{
    const float* x1      = (const float*)d_in[0];
    const float* x2      = (const float*)d_in[1];
    const float* conv1_w = (const float*)d_in[2];
    const float* conv1_b = (const float*)d_in[3];
    const float* conv2_w = (const float*)d_in[4];
    const float* conv2_b = (const float*)d_in[5];
    const float* norm_w  = (const float*)d_in[6];
    const float* norm_b  = (const float*)d_in[7];
    const float* ni_w    = (const float*)d_in[8];
    const float* ni_b    = (const float*)d_in[9];
    const float* ns_w    = (const float*)d_in[10];
    const float* ns_b    = (const float*)d_in[11];
    const float* nm_w    = (const float*)d_in[12];
    const float* nm_b    = (const float*)d_in[13];
    const float* slots_mu        = (const float*)d_in[14];
    const float* slots_log_sigma = (const float*)d_in[15];
    const float* Wq      = (const float*)d_in[16];
    const float* Wk      = (const float*)d_in[17];
    const float* Wv      = (const float*)d_in[18];
    const float* gru_wih = (const float*)d_in[19];
    const float* gru_whh = (const float*)d_in[20];
    const float* gru_bih = (const float*)d_in[21];
    const float* gru_bhh = (const float*)d_in[22];
    const float* mlp_w1  = (const float*)d_in[23];
    const float* mlp_b1  = (const float*)d_in[24];
    const float* mlp_w2  = (const float*)d_in[25];
    const float* mlp_b2  = (const float*)d_in[26];
    const float* head_w  = (const float*)d_in[27];
    const float* head_b  = (const float*)d_in[28];
    const float* noise   = (const float*)d_in[29];
    float* out = (float*)d_out;

    cudaFuncSetAttribute(conv_ln_kv_kernel,
                         cudaFuncAttributeMaxDynamicSharedMemorySize, SM_TOTAL);

    init_slots_kernel<<<256, 256>>>(slots_mu, slots_log_sigma, noise);    // 0
    wprep_kernel<<<240, 256>>>(conv1_w, conv2_w, Wk, Wv,                  // 1
                               gru_wih, gru_whh, mlp_w1, mlp_w2);
    slot_q_kernel<<<128, 512>>>(ns_w, ns_b, Wq);                          // 2
    dim3 g1(8, 2, 128);
    conv_ln_kv_kernel<<<g1, 256, SM_TOTAL>>>(x1, x2, conv1_b, conv2_b,    // 3
                                             norm_w, norm_b, ni_w, ni_b);

    for (int it = 0; it < 3; ++it) {
        attn_update_kernel<<<dim3(8, 128), 256>>>();
        gru_mlp_kernel<<<128, 512>>>(gru_bih, gru_bhh, nm_w, nm_b,
                                     mlp_b1, mlp_b2, ns_w, ns_b, Wq,
                                     (it < 2) ? 1 : 0);
    }
    head_kernel<<<128, 64>>>(head_w, head_b, out);
}

// round 15
// speedup vs baseline: 1.0040x; 1.0040x over previous
#include <cuda_runtime.h>
#include <cuda_bf16.h>
#include <cstdint>
#include <math.h>

// ---------------- scratch ---------------------------------------------------
__device__ uint32_t g_kb[128u * 2048u * 32u];   // k bf16 [B][N][64]
__device__ uint32_t g_vb[128u * 2048u * 32u];   // v bf16
__device__ float4   g_q4[128u * 8u * 16u];      // q fp32 [B,S,64]
__device__ float    g_slots[128 * 8 * 64];
__device__ float    g_csP[8 * 128 * 8];
__device__ float    g_updp[8 * 128 * 8 * 64];
__device__ uint32_t g_cwb[2][8192];             // conv W bf16 [64][256]/2
__device__ uint32_t g_wkb[2048], g_wvb[2048];   // Wk/Wv bf16 [64][64]/2
__device__ float    g_wihT[12288];              // [c][192]
__device__ float    g_whhT[12288];              // [c][192]
__device__ float    g_w1T[8192];                // [c][128]
__device__ float    g_w2T[8192];                // [j][64]

// ---------------- helpers ---------------------------------------------------
__device__ __forceinline__ void mma16816(float* c, const uint32_t* a,
                                         uint32_t b0, uint32_t b1) {
    asm volatile(
        "mma.sync.aligned.m16n8k16.row.col.f32.bf16.bf16.f32 "
        "{%0,%1,%2,%3}, {%4,%5,%6,%7}, {%8,%9}, {%0,%1,%2,%3};"
        : "+f"(c[0]), "+f"(c[1]), "+f"(c[2]), "+f"(c[3])
        : "r"(a[0]), "r"(a[1]), "r"(a[2]), "r"(a[3]), "r"(b0), "r"(b1));
}
__device__ __forceinline__ void ldsm_x4(uint32_t* r, uint32_t addr) {
    asm volatile("ldmatrix.sync.aligned.m8n8.x4.shared.b16 {%0,%1,%2,%3}, [%4];"
                 : "=r"(r[0]), "=r"(r[1]), "=r"(r[2]), "=r"(r[3]) : "r"(addr));
}
__device__ __forceinline__ void ldsm_x4_t(uint32_t* r, uint32_t addr) {
    asm volatile("ldmatrix.sync.aligned.m8n8.x4.trans.shared.b16 {%0,%1,%2,%3}, [%4];"
                 : "=r"(r[0]), "=r"(r[1]), "=r"(r[2]), "=r"(r[3]) : "r"(addr));
}
__device__ __forceinline__ uint32_t smem_u32(const void* p) {
    uint32_t a;
    asm("{ .reg .u64 t; cvta.to.shared.u64 t, %1; cvt.u32.u64 %0, t; }"
        : "=r"(a) : "l"(p));
    return a;
}
__device__ __forceinline__ uint32_t pack2(float a, float b) {
    __nv_bfloat162 h;
    h.x = __float2bfloat16_rn(a);
    h.y = __float2bfloat16_rn(b);
    return *(uint32_t*)&h;
}
__device__ __forceinline__ float2 bf2f(uint32_t u) {
    return __bfloat1622float2(*(__nv_bfloat162*)&u);
}

// conv smem layout
#define SX 136
#define SKD 72
#define OFF_XB0  0u
#define OFF_XB1  17408u
#define OFF_WB0  34816u
#define OFF_WB1  44032u
#define OFF_WK   53248u
#define OFF_WV   62464u
#define SM_TOTAL 71680u
#define OFF_YS    0u
#define OFF_A2    34816u
#define OFF_STAGE 0u

// ===========================================================================
// Kernel 0a: init slots
// ===========================================================================
__global__ void init_slots_kernel(const float* __restrict__ mu,
                                  const float* __restrict__ ls,
                                  const float* __restrict__ noise)
{
    int i = blockIdx.x * 256 + threadIdx.x;
    int d = i & 63;
    g_slots[i] = mu[d] + expf(ls[d]) * noise[i];
}

// ===========================================================================
// Kernel 0b: weight prep
// ===========================================================================
__global__ void wprep_kernel(const float* __restrict__ cw1,
                             const float* __restrict__ cw2,
                             const float* __restrict__ Wk,
                             const float* __restrict__ Wv,
                             const float* __restrict__ wih,
                             const float* __restrict__ whh,
                             const float* __restrict__ w1,
                             const float* __restrict__ w2)
{
    int i = blockIdx.x * 256 + threadIdx.x;
    if (i < 8192) {
        g_cwb[0][i] = pack2(cw1[2 * i], cw1[2 * i + 1]);
    } else if (i < 16384) {
        int j = i - 8192;
        g_cwb[1][j] = pack2(cw2[2 * j], cw2[2 * j + 1]);
    } else if (i < 18432) {
        int j = i - 16384;
        g_wkb[j] = pack2(Wk[2 * j], Wk[2 * j + 1]);
    } else if (i < 20480) {
        int j = i - 18432;
        g_wvb[j] = pack2(Wv[2 * j], Wv[2 * j + 1]);
    } else if (i < 32768) {
        int j = i - 20480;
        int c = j / 192, row = j % 192;
        g_wihT[j] = wih[row * 64 + c];
    } else if (i < 45056) {
        int j = i - 32768;
        int c = j / 192, row = j % 192;
        g_whhT[j] = whh[row * 64 + c];
    } else if (i < 53248) {
        int j = i - 45056;
        int c = j / 128, col = j % 128;
        g_w1T[j] = w1[col * 64 + c];
    } else if (i < 61440) {
        int j3 = i - 53248;
        int j = j3 / 64, d = j3 % 64;
        g_w2T[j3] = w2[d * 128 + j];
    }
}

// ===========================================================================
// Kernel slot_q (initial q only). grid B, block 512
// ===========================================================================
__global__ void slot_q_kernel(const float* __restrict__ ns_w,
                              const float* __restrict__ ns_b,
                              const float* __restrict__ Wq)
{
    __shared__ float sn[8][64];
    __shared__ float Wqt[64][65];
    __shared__ float wsum[16], wsq[16];
    const int b = blockIdx.x;
    const int tid = threadIdx.x;
    const int s = tid >> 6, d = tid & 63;

#pragma unroll
    for (int j = 0; j < 8; ++j) {
        int lin = j * 512 + tid;
        int e = lin >> 6, c = lin & 63;
        Wqt[c][e] = Wq[lin];
    }
    float v = g_slots[(b * 8 + s) * 64 + d];
    float su = v, sq = v * v;
#pragma unroll
    for (int o = 16; o > 0; o >>= 1) {
        su += __shfl_xor_sync(0xffffffffu, su, o);
        sq += __shfl_xor_sync(0xffffffffu, sq, o);
    }
    if ((tid & 31) == 0) { wsum[tid >> 5] = su; wsq[tid >> 5] = sq; }
    __syncthreads();
    float ts = wsum[s * 2] + wsum[s * 2 + 1];
    float tq = wsq[s * 2] + wsq[s * 2 + 1];
    float mu = ts * (1.f / 64.f);
    float inv = rsqrtf(tq * (1.f / 64.f) - mu * mu + 1e-5f);
    sn[s][d] = (v - mu) * inv * ns_w[d] + ns_b[d];
    __syncthreads();
    float acc = 0.f;
#pragma unroll
    for (int c = 0; c < 64; ++c) acc += sn[s][c] * Wqt[c][d];
    ((float*)g_q4)[(b * 8 + s) * 64 + d] = acc * 0.125f;
}

// ===========================================================================
// Kernel 1 (profiled slot): conv (pipelined) -> LN -> LN -> k,v GEMMs
// ===========================================================================
__global__ __launch_bounds__(256)
void conv_ln_kv_kernel(
    const float* __restrict__ x1, const float* __restrict__ x2,
    const float* __restrict__ cb1, const float* __restrict__ cb2,
    const float* __restrict__ norm_w, const float* __restrict__ norm_b,
    const float* __restrict__ ni_w,  const float* __restrict__ ni_b)
{
    extern __shared__ char smem[];
    const uint32_t sb = smem_u32(smem);
    const int tid = threadIdx.x;
    const int w = tid >> 5, lane = tid & 31;
    const int g = lane >> 2, tg = lane & 3;
    const int rowin = lane & 7, quad = lane >> 3;
    const int M0 = (w & 3) * 16;
    const int N0 = (w >> 2) * 64;
    const int b = blockIdx.z, src = blockIdx.y;
    const int p0 = blockIdx.x * 128;

    const float* X    = (src ? x2 : x1) + (size_t)b * 262144 + p0;
    const float* bias = src ? cb2 : cb1;
    const uint4* Wsrc = (const uint4*)(g_cwb[src]);

    const uint32_t laneW  = (uint32_t)(((M0 + rowin + (quad & 1) * 8) * SKD
                                        + (quad >> 1) * 8) * 2);
    const uint32_t laneBX = (uint32_t)(((rowin + (quad & 1) * 8) * SX
                                        + N0 + (quad >> 1) * 8) * 2);
    const uint32_t laneB2 = (uint32_t)(((rowin + (quad >> 1) * 8) * SKD
                                        + (quad & 1) * 8) * 2);

#pragma unroll
    for (int it = 0; it < 2; ++it) {
        int idx = it * 256 + tid;
        int e = idx >> 3, q = idx & 7;
        *(uint4*)(smem + OFF_WK + (uint32_t)(e * 144 + q * 16)) =
            ((const uint4*)g_wkb)[e * 8 + q];
        *(uint4*)(smem + OFF_WV + (uint32_t)(e * 144 + q * 16)) =
            ((const uint4*)g_wvb)[e * 8 + q];
    }

    // prologue: chunk 0 -> buf0
#pragma unroll
    for (int it = 0; it < 8; ++it) {
        int idx = it * 256 + tid;
        int ch = idx >> 5, p4 = idx & 31;
        float4 x4 = *(const float4*)(X + (size_t)ch * 1024 + p4 * 4);
        uint2 pr;
        pr.x = pack2(x4.x, x4.y);
        pr.y = pack2(x4.z, x4.w);
        *(uint2*)(smem + OFF_XB0 + (uint32_t)((ch * SX + p4 * 4) * 2)) = pr;
    }
#pragma unroll
    for (int it = 0; it < 2; ++it) {
        int idx = it * 256 + tid;
        int d = idx >> 3, q = idx & 7;
        *(uint4*)(smem + OFF_WB0 + (uint32_t)(d * 144 + q * 16)) =
            Wsrc[d * 32 + q];
    }
    __syncthreads();

    float acc[8][4];
#pragma unroll
    for (int nf = 0; nf < 8; ++nf)
#pragma unroll
        for (int i = 0; i < 4; ++i) acc[nf][i] = 0.f;

    const uint32_t xoff[2] = {OFF_XB0, OFF_XB1};
    const uint32_t woff[2] = {OFF_WB0, OFF_WB1};

#pragma unroll
    for (int chunk = 0; chunk < 4; ++chunk) {
        const int cur = chunk & 1;
        float4 xv[8];
        uint4 wv[2];
        if (chunk < 3) {
            const int cb = (chunk + 1) * 64;
#pragma unroll
            for (int it = 0; it < 8; ++it) {
                int idx = it * 256 + tid;
                int ch = idx >> 5, p4 = idx & 31;
                xv[it] = *(const float4*)(X + (size_t)(cb + ch) * 1024 + p4 * 4);
            }
#pragma unroll
            for (int it = 0; it < 2; ++it) {
                int idx = it * 256 + tid;
                int d = idx >> 3, q = idx & 7;
                wv[it] = Wsrc[d * 32 + (chunk + 1) * 8 + q];
            }
        }
        const uint32_t xb = sb + xoff[cur];
        const uint32_t wb = sb + woff[cur];
#pragma unroll
        for (int ks = 0; ks < 4; ++ks) {
            uint32_t ah[4], bx[4];
            ldsm_x4(ah, wb + laneW + ks * 32);
#pragma unroll
            for (int nfp = 0; nfp < 4; ++nfp) {
                ldsm_x4_t(bx, xb + laneBX
                              + (uint32_t)(ks * 16 * SX * 2) + nfp * 32);
                mma16816(acc[2 * nfp],     ah, bx[0], bx[1]);
                mma16816(acc[2 * nfp + 1], ah, bx[2], bx[3]);
            }
        }
        if (chunk < 3) {
            const int nxt = cur ^ 1;
#pragma unroll
            for (int it = 0; it < 8; ++it) {
                int idx = it * 256 + tid;
                int ch = idx >> 5, p4 = idx & 31;
                uint2 pr;
                pr.x = pack2(xv[it].x, xv[it].y);
                pr.y = pack2(xv[it].z, xv[it].w);
                *(uint2*)(smem + xoff[nxt] +
                          (uint32_t)((ch * SX + p4 * 4) * 2)) = pr;
            }
#pragma unroll
            for (int it = 0; it < 2; ++it) {
                int idx = it * 256 + tid;
                int d = idx >> 3, q = idx & 7;
                *(uint4*)(smem + woff[nxt] + (uint32_t)(d * 144 + q * 16)) =
                    wv[it];
            }
        }
        __syncthreads();
    }

    float* Ys = (float*)(smem + OFF_YS);
    {
        float b0 = bias[M0 + g], b8 = bias[M0 + g + 8];
#pragma unroll
        for (int nf = 0; nf < 8; ++nf) {
            int p = N0 + nf * 8 + 2 * tg;
            Ys[p * 65 + M0 + g]           = acc[nf][0] + b0;
            Ys[(p + 1) * 65 + M0 + g]     = acc[nf][1] + b0;
            Ys[p * 65 + M0 + g + 8]       = acc[nf][2] + b8;
            Ys[(p + 1) * 65 + M0 + g + 8] = acc[nf][3] + b8;
        }
    }
    __syncthreads();

    if (tid < 128) {
        float* row = Ys + tid * 65;
        float s = 0.f, q = 0.f;
#pragma unroll
        for (int d = 0; d < 64; ++d) { float v = row[d]; s += v; q += v * v; }
        float mu = s * (1.f / 64.f);
        float inv = rsqrtf(q * (1.f / 64.f) - mu * mu + 1e-5f);
        s = 0.f; q = 0.f;
#pragma unroll
        for (int d = 0; d < 64; ++d) {
            float y = (row[d] - mu) * inv * norm_w[d] + norm_b[d];
            row[d] = y; s += y; q += y * y;
        }
        mu = s * (1.f / 64.f);
        inv = rsqrtf(q * (1.f / 64.f) - mu * mu + 1e-5f);
#pragma unroll
        for (int d = 0; d < 64; ++d)
            row[d] = (row[d] - mu) * inv * ni_w[d] + ni_b[d];
    }
    __syncthreads();

#pragma unroll
    for (int it = 0; it < 16; ++it) {
        int idx = it * 256 + tid;
        int p = idx >> 5, d2 = idx & 31;
        *(uint32_t*)(smem + OFF_A2 + (uint32_t)((p * SKD + 2 * d2) * 2)) =
            pack2(Ys[p * 65 + 2 * d2], Ys[p * 65 + 2 * d2 + 1]);
    }
    __syncthreads();

    uint32_t* kb = g_kb + (size_t)(b * 2048 + src * 1024 + p0) * 32;
    uint32_t* vb = g_vb + (size_t)(b * 2048 + src * 1024 + p0) * 32;
    float* stage = (float*)(smem + OFF_STAGE);

#pragma unroll
    for (int mat = 0; mat < 2; ++mat) {
        uint32_t Bbase = sb + (mat ? OFF_WV : OFF_WK);
        uint32_t* outb = mat ? vb : kb;
        float ac[8][4];
#pragma unroll
        for (int nf = 0; nf < 8; ++nf)
#pragma unroll
            for (int i = 0; i < 4; ++i) ac[nf][i] = 0.f;
#pragma unroll
        for (int ks = 0; ks < 4; ++ks) {
            uint32_t ah[4], bx[4];
            ldsm_x4(ah, Bbase + laneW + ks * 32);
#pragma unroll
            for (int nfp = 0; nfp < 4; ++nfp) {
                ldsm_x4(bx, sb + OFF_A2 + laneB2
                            + (uint32_t)((N0 + nfp * 16) * SKD * 2) + ks * 32);
                mma16816(ac[2 * nfp],     ah, bx[0], bx[1]);
                mma16816(ac[2 * nfp + 1], ah, bx[2], bx[3]);
            }
        }
#pragma unroll
        for (int nf = 0; nf < 8; ++nf) {
            int p = N0 + nf * 8 + 2 * tg;
            int e = M0 + g;
            stage[p * 64 + e]           = ac[nf][0];
            stage[(p + 1) * 64 + e]     = ac[nf][1];
            stage[p * 64 + e + 8]       = ac[nf][2];
            stage[(p + 1) * 64 + e + 8] = ac[nf][3];
        }
        __syncthreads();
#pragma unroll
        for (int j = 0; j < 16; ++j) {
            int idx = j * 256 + tid;
            float2 f = ((const float2*)stage)[idx];
            outb[idx] = pack2(f.x, f.y);
        }
        __syncthreads();
    }
}

// ===========================================================================
// attn_update (direct gmem k reads, static smem). grid (8,B), block 256
// ===========================================================================
__global__ void attn_update_kernel()
{
    __shared__ float qs[8][64];
    __shared__ float csw[8][8];
    __shared__ float attn_s[256][8];
    __shared__ float4 red[16][128];
    const int sp = blockIdx.x, b = blockIdx.y;
    const int tid = threadIdx.x;
    const int w = tid >> 5, lane = tid & 31;
    const int t = sp * 256 + tid;

    ((float*)qs)[tid]       = ((const float*)g_q4)[b * 512 + tid];
    ((float*)qs)[tid + 256] = ((const float*)g_q4)[b * 512 + tid + 256];
    __syncthreads();

    const uint4* kr = (const uint4*)(g_kb + ((size_t)b * 2048 + t) * 32);
    float a[8];
#pragma unroll
    for (int s = 0; s < 8; ++s) a[s] = 0.f;
#pragma unroll
    for (int i = 0; i < 8; ++i) {
        uint4 A = kr[i];
        float2 f0 = bf2f(A.x), f1 = bf2f(A.y), f2 = bf2f(A.z), f3 = bf2f(A.w);
#pragma unroll
        for (int s = 0; s < 8; ++s) {
            const float* q8 = &qs[s][8 * i];
            a[s] = fmaf(f0.x, q8[0], fmaf(f0.y, q8[1],
                   fmaf(f1.x, q8[2], fmaf(f1.y, q8[3],
                   fmaf(f2.x, q8[4], fmaf(f2.y, q8[5],
                   fmaf(f3.x, q8[6], fmaf(f3.y, q8[7], a[s]))))))));
        }
    }
    float mx = a[0];
#pragma unroll
    for (int s = 1; s < 8; ++s) mx = fmaxf(mx, a[s]);
    float sm = 0.f;
#pragma unroll
    for (int s = 0; s < 8; ++s) { a[s] = __expf(a[s] - mx); sm += a[s]; }
    float rv = 1.f / sm;
#pragma unroll
    for (int s = 0; s < 8; ++s) a[s] = a[s] * rv + 1e-8f;

    *(float4*)&attn_s[tid][0] = make_float4(a[0], a[1], a[2], a[3]);
    *(float4*)&attn_s[tid][4] = make_float4(a[4], a[5], a[6], a[7]);

#pragma unroll
    for (int s = 0; s < 8; ++s) {
        float v = a[s];
#pragma unroll
        for (int o = 16; o > 0; o >>= 1) v += __shfl_xor_sync(0xffffffffu, v, o);
        if (lane == 0) csw[w][s] = v;
    }
    __syncthreads();
    if (tid < 8) {
        float tt = 0.f;
#pragma unroll
        for (int ww = 0; ww < 8; ++ww) tt += csw[ww][tid];
        g_csP[sp * 1024 + b * 8 + tid] = tt;
    }

    const int dq = tid & 15, grp = tid >> 4;
    const uint2* V2 = (const uint2*)(g_vb + ((size_t)b * 2048 + sp * 256) * 32);
    float4 acc[8];
#pragma unroll
    for (int s = 0; s < 8; ++s) acc[s] = make_float4(0.f, 0.f, 0.f, 0.f);
#pragma unroll 4
    for (int j = 0; j < 16; ++j) {
        int tt = grp * 16 + j;
        uint2 vv = V2[tt * 16 + dq];
        float2 v01 = bf2f(vv.x), v23 = bf2f(vv.y);
        float4 A01 = *(const float4*)&attn_s[tt][0];
        float4 A23 = *(const float4*)&attn_s[tt][4];
        const float aw[8] = {A01.x, A01.y, A01.z, A01.w,
                             A23.x, A23.y, A23.z, A23.w};
#pragma unroll
        for (int s = 0; s < 8; ++s) {
            acc[s].x = fmaf(aw[s], v01.x, acc[s].x);
            acc[s].y = fmaf(aw[s], v01.y, acc[s].y);
            acc[s].z = fmaf(aw[s], v23.x, acc[s].z);
            acc[s].w = fmaf(aw[s], v23.y, acc[s].w);
        }
    }
#pragma unroll
    for (int s = 0; s < 8; ++s) red[grp][s * 16 + dq] = acc[s];
    __syncthreads();
    if (tid < 128) {
        float4 r = make_float4(0.f, 0.f, 0.f, 0.f);
#pragma unroll
        for (int q = 0; q < 16; ++q) {
            float4 tt = red[q][tid];
            r.x += tt.x; r.y += tt.y; r.z += tt.z; r.w += tt.w;
        }
        ((float4*)g_updp)[sp * 16384 + b * 128 + tid] = r;
    }
}

// ===========================================================================
// gru_mlp (fast shape: grid 256, block 256, 4 slots/block) + appended q.
// ===========================================================================
__global__ void gru_mlp_kernel(
    const float* __restrict__ bih, const float* __restrict__ bhh,
    const float* __restrict__ nm_w, const float* __restrict__ nm_b,
    const float* __restrict__ b1, const float* __restrict__ b2,
    const float* __restrict__ ns_w, const float* __restrict__ ns_b,
    const float* __restrict__ Wq, int do_q)
{
    const int blk = blockIdx.x;
    const int tid = threadIdx.x;
    const int ls = tid >> 6, d = tid & 63;
    const int bs = blk * 4 + ls;
    __shared__ float u[4][64], sp_s[4][64], h[4][64], hh[4][128], r4[4][4];
    __shared__ float Wqt[64][65];

    if (do_q) {
#pragma unroll
        for (int j = 0; j < 16; ++j) {
            int lin = j * 256 + tid;
            Wqt[lin & 63][lin >> 6] = Wq[lin];
        }
    }
    float uacc = 0.f;
#pragma unroll
    for (int p = 0; p < 8; ++p) uacc += g_updp[p * 65536 + bs * 64 + d];
    float cs = 0.f;
#pragma unroll
    for (int p = 0; p < 8; ++p) cs += g_csP[p * 1024 + bs];
    u[ls][d]  = uacc / cs;
    sp_s[ls][d] = g_slots[bs * 64 + d];
    __syncthreads();

    float a0 = bih[d], a1 = bih[64 + d], a2 = bih[128 + d];
    float g0 = bhh[d], g1 = bhh[64 + d], g2 = bhh[128 + d];
#pragma unroll 8
    for (int c = 0; c < 64; ++c) {
        float uc = u[ls][c], sc = sp_s[ls][c];
        const float* wi = g_wihT + c * 192;
        const float* wh = g_whhT + c * 192;
        a0 = fmaf(uc, wi[d], a0);
        a1 = fmaf(uc, wi[64 + d], a1);
        a2 = fmaf(uc, wi[128 + d], a2);
        g0 = fmaf(sc, wh[d], g0);
        g1 = fmaf(sc, wh[64 + d], g1);
        g2 = fmaf(sc, wh[128 + d], g2);
    }
    float r = 1.f / (1.f + __expf(-(a0 + g0)));
    float z = 1.f / (1.f + __expf(-(a1 + g1)));
    float nn = tanhf(a2 + r * g2);
    float sl = (1.f - z) * nn + z * sp_s[ls][d];

    float su = sl, sq = sl * sl;
#pragma unroll
    for (int o = 16; o > 0; o >>= 1) {
        su += __shfl_xor_sync(0xffffffffu, su, o);
        sq += __shfl_xor_sync(0xffffffffu, sq, o);
    }
    if ((d & 31) == 0) { r4[ls][d >> 5] = su; r4[ls][2 + (d >> 5)] = sq; }
    __syncthreads();
    float ts = r4[ls][0] + r4[ls][1], tq = r4[ls][2] + r4[ls][3];
    float mu = ts * (1.f / 64.f);
    float inv = rsqrtf(tq * (1.f / 64.f) - mu * mu + 1e-5f);
    h[ls][d] = (sl - mu) * inv * nm_w[d] + nm_b[d];
    __syncthreads();

    float m0 = b1[d], m1 = b1[64 + d];
#pragma unroll 8
    for (int c = 0; c < 64; ++c) {
        float hc = h[ls][c];
        const float* w1r = g_w1T + c * 128;
        m0 = fmaf(hc, w1r[d], m0);
        m1 = fmaf(hc, w1r[64 + d], m1);
    }
    hh[ls][d] = fmaxf(m0, 0.f);
    hh[ls][64 + d] = fmaxf(m1, 0.f);
    __syncthreads();

    float o = b2[d];
#pragma unroll 8
    for (int j = 0; j < 128; ++j)
        o = fmaf(hh[ls][j], g_w2T[j * 64 + d], o);
    float newslot = sl + o;
    g_slots[bs * 64 + d] = newslot;

    if (do_q) {
        __syncthreads();          // u no longer read; safe to reuse
        float su2 = newslot, sq2 = newslot * newslot;
#pragma unroll
        for (int o2 = 16; o2 > 0; o2 >>= 1) {
            su2 += __shfl_xor_sync(0xffffffffu, su2, o2);
            sq2 += __shfl_xor_sync(0xffffffffu, sq2, o2);
        }
        if ((d & 31) == 0) { r4[ls][d >> 5] = su2; r4[ls][2 + (d >> 5)] = sq2; }
        __syncthreads();
        float ts2 = r4[ls][0] + r4[ls][1], tq2 = r4[ls][2] + r4[ls][3];
        float mu2 = ts2 * (1.f / 64.f);
        float inv2 = rsqrtf(tq2 * (1.f / 64.f) - mu2 * mu2 + 1e-5f);
        u[ls][d] = (newslot - mu2) * inv2 * ns_w[d] + ns_b[d];
        __syncthreads();
        float acc = 0.f;
#pragma unroll
        for (int c = 0; c < 64; ++c) acc += u[ls][c] * Wqt[c][d];
        ((float*)g_q4)[bs * 64 + d] = acc * 0.125f;
    }
}

// ===========================================================================
// Kernel 7: head
// ===========================================================================
__global__ void head_kernel(const float* __restrict__ head_w,
                            const float* __restrict__ head_b,
                            float* __restrict__ out)
{
    const int b = blockIdx.x;
    const int d = threadIdx.x;
    __shared__ float f[64];
    float a = 0.f;
#pragma unroll
    for (int s = 0; s < 8; ++s) a += g_slots[(b * 8 + s) * 64 + d];
    f[d] = a * 0.125f;
    __syncthreads();
    if (d < 15) {
        float o = head_b[d];
        const float* hw = head_w + d * 64;
#pragma unroll
        for (int c = 0; c < 64; ++c) o += f[c] * hw[c];
        out[b * 15 + d] = o;
    }
}

// ===========================================================================
extern "C" void kernel_launch(void* const* d_in, const int* in_sizes, int n_in,
                              void* d_out, int out_size)
{
    const float* x1      = (const float*)d_in[0];
    const float* x2      = (const float*)d_in[1];
    const float* conv1_w = (const float*)d_in[2];
    const float* conv1_b = (const float*)d_in[3];
    const float* conv2_w = (const float*)d_in[4];
    const float* conv2_b = (const float*)d_in[5];
    const float* norm_w  = (const float*)d_in[6];
    const float* norm_b  = (const float*)d_in[7];
    const float* ni_w    = (const float*)d_in[8];
    const float* ni_b    = (const float*)d_in[9];
    const float* ns_w    = (const float*)d_in[10];
    const float* ns_b    = (const float*)d_in[11];
    const float* nm_w    = (const float*)d_in[12];
    const float* nm_b    = (const float*)d_in[13];
    const float* slots_mu        = (const float*)d_in[14];
    const float* slots_log_sigma = (const float*)d_in[15];
    const float* Wq      = (const float*)d_in[16];
    const float* Wk      = (const float*)d_in[17];
    const float* Wv      = (const float*)d_in[18];
    const float* gru_wih = (const float*)d_in[19];
    const float* gru_whh = (const float*)d_in[20];
    const float* gru_bih = (const float*)d_in[21];
    const float* gru_bhh = (const float*)d_in[22];
    const float* mlp_w1  = (const float*)d_in[23];
    const float* mlp_b1  = (const float*)d_in[24];
    const float* mlp_w2  = (const float*)d_in[25];
    const float* mlp_b2  = (const float*)d_in[26];
    const float* head_w  = (const float*)d_in[27];
    const float* head_b  = (const float*)d_in[28];
    const float* noise   = (const float*)d_in[29];
    float* out = (float*)d_out;

    cudaFuncSetAttribute(conv_ln_kv_kernel,
                         cudaFuncAttributeMaxDynamicSharedMemorySize, SM_TOTAL);

    init_slots_kernel<<<256, 256>>>(slots_mu, slots_log_sigma, noise);    // 0
    wprep_kernel<<<240, 256>>>(conv1_w, conv2_w, Wk, Wv,                  // 1
                               gru_wih, gru_whh, mlp_w1, mlp_w2);
    slot_q_kernel<<<128, 512>>>(ns_w, ns_b, Wq);                          // 2
    dim3 g1(8, 2, 128);
    conv_ln_kv_kernel<<<g1, 256, SM_TOTAL>>>(x1, x2, conv1_b, conv2_b,    // 3
                                             norm_w, norm_b, ni_w, ni_b);

    for (int it = 0; it < 3; ++it) {
        attn_update_kernel<<<dim3(8, 128), 256>>>();
        gru_mlp_kernel<<<256, 256>>>(gru_bih, gru_bhh, nm_w, nm_b,
                                     mlp_b1, mlp_b2, ns_w, ns_b, Wq,
                                     (it < 2) ? 1 : 0);
    }
    head_kernel<<<128, 64>>>(head_w, head_b, out);
}

// round 16
// speedup vs baseline: 1.0784x; 1.0741x over previous
#include <cuda_runtime.h>
#include <cuda_bf16.h>
#include <cstdint>
#include <math.h>

// ---------------- scratch ---------------------------------------------------
__device__ uint32_t g_kb[128u * 2048u * 32u];   // k bf16 [B][N][64]
__device__ uint32_t g_vb[128u * 2048u * 32u];   // v bf16
__device__ float4   g_q4[128u * 8u * 16u];      // q fp32 [B,S,64]
__device__ float    g_slots[128 * 8 * 64];
__device__ float    g_csP[8 * 128 * 8];
__device__ float    g_updp[8 * 128 * 8 * 64];
__device__ uint32_t g_cwb[2][8192];             // conv W bf16 [64][256]/2
__device__ uint32_t g_wkb[2048], g_wvb[2048];   // Wk/Wv bf16 [64][64]/2
__device__ float    g_wihT[12288];              // [c][192]
__device__ float    g_whhT[12288];              // [c][192]
__device__ float    g_w1T[8192];                // [c][128]
__device__ float    g_w2T[8192];                // [j][64]

// ---------------- helpers ---------------------------------------------------
__device__ __forceinline__ void mma16816(float* c, const uint32_t* a,
                                         uint32_t b0, uint32_t b1) {
    asm volatile(
        "mma.sync.aligned.m16n8k16.row.col.f32.bf16.bf16.f32 "
        "{%0,%1,%2,%3}, {%4,%5,%6,%7}, {%8,%9}, {%0,%1,%2,%3};"
        : "+f"(c[0]), "+f"(c[1]), "+f"(c[2]), "+f"(c[3])
        : "r"(a[0]), "r"(a[1]), "r"(a[2]), "r"(a[3]), "r"(b0), "r"(b1));
}
__device__ __forceinline__ void ldsm_x4(uint32_t* r, uint32_t addr) {
    asm volatile("ldmatrix.sync.aligned.m8n8.x4.shared.b16 {%0,%1,%2,%3}, [%4];"
                 : "=r"(r[0]), "=r"(r[1]), "=r"(r[2]), "=r"(r[3]) : "r"(addr));
}
__device__ __forceinline__ void ldsm_x4_t(uint32_t* r, uint32_t addr) {
    asm volatile("ldmatrix.sync.aligned.m8n8.x4.trans.shared.b16 {%0,%1,%2,%3}, [%4];"
                 : "=r"(r[0]), "=r"(r[1]), "=r"(r[2]), "=r"(r[3]) : "r"(addr));
}
__device__ __forceinline__ uint32_t smem_u32(const void* p) {
    uint32_t a;
    asm("{ .reg .u64 t; cvta.to.shared.u64 t, %1; cvt.u32.u64 %0, t; }"
        : "=r"(a) : "l"(p));
    return a;
}
__device__ __forceinline__ uint32_t pack2(float a, float b) {
    __nv_bfloat162 h;
    h.x = __float2bfloat16_rn(a);
    h.y = __float2bfloat16_rn(b);
    return *(uint32_t*)&h;
}
__device__ __forceinline__ float2 bf2f(uint32_t u) {
    return __bfloat1622float2(*(__nv_bfloat162*)&u);
}

// conv smem layout
#define SX 136
#define SKD 72
#define OFF_XB0  0u
#define OFF_XB1  17408u
#define OFF_WB0  34816u
#define OFF_WB1  44032u
#define OFF_WK   53248u
#define OFF_WV   62464u
#define SM_TOTAL 71680u
#define OFF_YS    0u
#define OFF_A2    34816u
#define OFF_STAGE 0u

// ===========================================================================
// Kernel 0a: init slots
// ===========================================================================
__global__ void init_slots_kernel(const float* __restrict__ mu,
                                  const float* __restrict__ ls,
                                  const float* __restrict__ noise)
{
    int i = blockIdx.x * 256 + threadIdx.x;
    int d = i & 63;
    g_slots[i] = mu[d] + expf(ls[d]) * noise[i];
}

// ===========================================================================
// Kernel 0b: weight prep
// ===========================================================================
__global__ void wprep_kernel(const float* __restrict__ cw1,
                             const float* __restrict__ cw2,
                             const float* __restrict__ Wk,
                             const float* __restrict__ Wv,
                             const float* __restrict__ wih,
                             const float* __restrict__ whh,
                             const float* __restrict__ w1,
                             const float* __restrict__ w2)
{
    int i = blockIdx.x * 256 + threadIdx.x;
    if (i < 8192) {
        g_cwb[0][i] = pack2(cw1[2 * i], cw1[2 * i + 1]);
    } else if (i < 16384) {
        int j = i - 8192;
        g_cwb[1][j] = pack2(cw2[2 * j], cw2[2 * j + 1]);
    } else if (i < 18432) {
        int j = i - 16384;
        g_wkb[j] = pack2(Wk[2 * j], Wk[2 * j + 1]);
    } else if (i < 20480) {
        int j = i - 18432;
        g_wvb[j] = pack2(Wv[2 * j], Wv[2 * j + 1]);
    } else if (i < 32768) {
        int j = i - 20480;
        int c = j / 192, row = j % 192;
        g_wihT[j] = wih[row * 64 + c];
    } else if (i < 45056) {
        int j = i - 32768;
        int c = j / 192, row = j % 192;
        g_whhT[j] = whh[row * 64 + c];
    } else if (i < 53248) {
        int j = i - 45056;
        int c = j / 128, col = j % 128;
        g_w1T[j] = w1[col * 64 + c];
    } else if (i < 61440) {
        int j3 = i - 53248;
        int j = j3 / 64, d = j3 % 64;
        g_w2T[j3] = w2[d * 128 + j];
    }
}

// ===========================================================================
// Kernel slot_q: q = LN(slots, ns) @ Wq^T * scale. grid B, block 512
// ===========================================================================
__global__ void slot_q_kernel(const float* __restrict__ ns_w,
                              const float* __restrict__ ns_b,
                              const float* __restrict__ Wq)
{
    __shared__ float sn[8][64];
    __shared__ float Wqt[64][65];
    __shared__ float wsum[16], wsq[16];
    const int b = blockIdx.x;
    const int tid = threadIdx.x;
    const int s = tid >> 6, d = tid & 63;

#pragma unroll
    for (int j = 0; j < 8; ++j) {
        int lin = j * 512 + tid;
        int e = lin >> 6, c = lin & 63;
        Wqt[c][e] = Wq[lin];
    }
    float v = g_slots[(b * 8 + s) * 64 + d];
    float su = v, sq = v * v;
#pragma unroll
    for (int o = 16; o > 0; o >>= 1) {
        su += __shfl_xor_sync(0xffffffffu, su, o);
        sq += __shfl_xor_sync(0xffffffffu, sq, o);
    }
    if ((tid & 31) == 0) { wsum[tid >> 5] = su; wsq[tid >> 5] = sq; }
    __syncthreads();
    float ts = wsum[s * 2] + wsum[s * 2 + 1];
    float tq = wsq[s * 2] + wsq[s * 2 + 1];
    float mu = ts * (1.f / 64.f);
    float inv = rsqrtf(tq * (1.f / 64.f) - mu * mu + 1e-5f);
    sn[s][d] = (v - mu) * inv * ns_w[d] + ns_b[d];
    __syncthreads();
    float acc = 0.f;
#pragma unroll
    for (int c = 0; c < 64; ++c) acc += sn[s][c] * Wqt[c][d];
    ((float*)g_q4)[(b * 8 + s) * 64 + d] = acc * 0.125f;
}

// ===========================================================================
// Kernel 1 (profiled slot): conv (pipelined, double-buffered) -> LN -> LN
// -> k,v GEMMs. grid (8, 2, 128) block 256
// ===========================================================================
__global__ __launch_bounds__(256)
void conv_ln_kv_kernel(
    const float* __restrict__ x1, const float* __restrict__ x2,
    const float* __restrict__ cb1, const float* __restrict__ cb2,
    const float* __restrict__ norm_w, const float* __restrict__ norm_b,
    const float* __restrict__ ni_w,  const float* __restrict__ ni_b)
{
    extern __shared__ char smem[];
    const uint32_t sb = smem_u32(smem);
    const int tid = threadIdx.x;
    const int w = tid >> 5, lane = tid & 31;
    const int g = lane >> 2, tg = lane & 3;
    const int rowin = lane & 7, quad = lane >> 3;
    const int M0 = (w & 3) * 16;
    const int N0 = (w >> 2) * 64;
    const int b = blockIdx.z, src = blockIdx.y;
    const int p0 = blockIdx.x * 128;

    const float* X    = (src ? x2 : x1) + (size_t)b * 262144 + p0;
    const float* bias = src ? cb2 : cb1;
    const uint4* Wsrc = (const uint4*)(g_cwb[src]);

    const uint32_t laneW  = (uint32_t)(((M0 + rowin + (quad & 1) * 8) * SKD
                                        + (quad >> 1) * 8) * 2);
    const uint32_t laneBX = (uint32_t)(((rowin + (quad & 1) * 8) * SX
                                        + N0 + (quad >> 1) * 8) * 2);
    const uint32_t laneB2 = (uint32_t)(((rowin + (quad >> 1) * 8) * SKD
                                        + (quad & 1) * 8) * 2);

#pragma unroll
    for (int it = 0; it < 2; ++it) {
        int idx = it * 256 + tid;
        int e = idx >> 3, q = idx & 7;
        *(uint4*)(smem + OFF_WK + (uint32_t)(e * 144 + q * 16)) =
            ((const uint4*)g_wkb)[e * 8 + q];
        *(uint4*)(smem + OFF_WV + (uint32_t)(e * 144 + q * 16)) =
            ((const uint4*)g_wvb)[e * 8 + q];
    }

    // prologue: chunk 0 -> buf0
#pragma unroll
    for (int it = 0; it < 8; ++it) {
        int idx = it * 256 + tid;
        int ch = idx >> 5, p4 = idx & 31;
        float4 x4 = *(const float4*)(X + (size_t)ch * 1024 + p4 * 4);
        uint2 pr;
        pr.x = pack2(x4.x, x4.y);
        pr.y = pack2(x4.z, x4.w);
        *(uint2*)(smem + OFF_XB0 + (uint32_t)((ch * SX + p4 * 4) * 2)) = pr;
    }
#pragma unroll
    for (int it = 0; it < 2; ++it) {
        int idx = it * 256 + tid;
        int d = idx >> 3, q = idx & 7;
        *(uint4*)(smem + OFF_WB0 + (uint32_t)(d * 144 + q * 16)) =
            Wsrc[d * 32 + q];
    }
    __syncthreads();

    float acc[8][4];
#pragma unroll
    for (int nf = 0; nf < 8; ++nf)
#pragma unroll
        for (int i = 0; i < 4; ++i) acc[nf][i] = 0.f;

    const uint32_t xoff[2] = {OFF_XB0, OFF_XB1};
    const uint32_t woff[2] = {OFF_WB0, OFF_WB1};

#pragma unroll
    for (int chunk = 0; chunk < 4; ++chunk) {
        const int cur = chunk & 1;
        float4 xv[8];
        uint4 wv[2];
        if (chunk < 3) {
            const int cb = (chunk + 1) * 64;
#pragma unroll
            for (int it = 0; it < 8; ++it) {
                int idx = it * 256 + tid;
                int ch = idx >> 5, p4 = idx & 31;
                xv[it] = *(const float4*)(X + (size_t)(cb + ch) * 1024 + p4 * 4);
            }
#pragma unroll
            for (int it = 0; it < 2; ++it) {
                int idx = it * 256 + tid;
                int d = idx >> 3, q = idx & 7;
                wv[it] = Wsrc[d * 32 + (chunk + 1) * 8 + q];
            }
        }
        const uint32_t xb = sb + xoff[cur];
        const uint32_t wb = sb + woff[cur];
#pragma unroll
        for (int ks = 0; ks < 4; ++ks) {
            uint32_t ah[4], bx[4];
            ldsm_x4(ah, wb + laneW + ks * 32);
#pragma unroll
            for (int nfp = 0; nfp < 4; ++nfp) {
                ldsm_x4_t(bx, xb + laneBX
                              + (uint32_t)(ks * 16 * SX * 2) + nfp * 32);
                mma16816(acc[2 * nfp],     ah, bx[0], bx[1]);
                mma16816(acc[2 * nfp + 1], ah, bx[2], bx[3]);
            }
        }
        if (chunk < 3) {
            const int nxt = cur ^ 1;
#pragma unroll
            for (int it = 0; it < 8; ++it) {
                int idx = it * 256 + tid;
                int ch = idx >> 5, p4 = idx & 31;
                uint2 pr;
                pr.x = pack2(xv[it].x, xv[it].y);
                pr.y = pack2(xv[it].z, xv[it].w);
                *(uint2*)(smem + xoff[nxt] +
                          (uint32_t)((ch * SX + p4 * 4) * 2)) = pr;
            }
#pragma unroll
            for (int it = 0; it < 2; ++it) {
                int idx = it * 256 + tid;
                int d = idx >> 3, q = idx & 7;
                *(uint4*)(smem + woff[nxt] + (uint32_t)(d * 144 + q * 16)) =
                    wv[it];
            }
        }
        __syncthreads();
    }

    float* Ys = (float*)(smem + OFF_YS);
    {
        float b0 = bias[M0 + g], b8 = bias[M0 + g + 8];
#pragma unroll
        for (int nf = 0; nf < 8; ++nf) {
            int p = N0 + nf * 8 + 2 * tg;
            Ys[p * 65 + M0 + g]           = acc[nf][0] + b0;
            Ys[(p + 1) * 65 + M0 + g]     = acc[nf][1] + b0;
            Ys[p * 65 + M0 + g + 8]       = acc[nf][2] + b8;
            Ys[(p + 1) * 65 + M0 + g + 8] = acc[nf][3] + b8;
        }
    }
    __syncthreads();

    if (tid < 128) {
        float* row = Ys + tid * 65;
        float s = 0.f, q = 0.f;
#pragma unroll
        for (int d = 0; d < 64; ++d) { float v = row[d]; s += v; q += v * v; }
        float mu = s * (1.f / 64.f);
        float inv = rsqrtf(q * (1.f / 64.f) - mu * mu + 1e-5f);
        s = 0.f; q = 0.f;
#pragma unroll
        for (int d = 0; d < 64; ++d) {
            float y = (row[d] - mu) * inv * norm_w[d] + norm_b[d];
            row[d] = y; s += y; q += y * y;
        }
        mu = s * (1.f / 64.f);
        inv = rsqrtf(q * (1.f / 64.f) - mu * mu + 1e-5f);
#pragma unroll
        for (int d = 0; d < 64; ++d)
            row[d] = (row[d] - mu) * inv * ni_w[d] + ni_b[d];
    }
    __syncthreads();

#pragma unroll
    for (int it = 0; it < 16; ++it) {
        int idx = it * 256 + tid;
        int p = idx >> 5, d2 = idx & 31;
        *(uint32_t*)(smem + OFF_A2 + (uint32_t)((p * SKD + 2 * d2) * 2)) =
            pack2(Ys[p * 65 + 2 * d2], Ys[p * 65 + 2 * d2 + 1]);
    }
    __syncthreads();

    uint32_t* kb = g_kb + (size_t)(b * 2048 + src * 1024 + p0) * 32;
    uint32_t* vb = g_vb + (size_t)(b * 2048 + src * 1024 + p0) * 32;
    float* stage = (float*)(smem + OFF_STAGE);

#pragma unroll
    for (int mat = 0; mat < 2; ++mat) {
        uint32_t Bbase = sb + (mat ? OFF_WV : OFF_WK);
        uint32_t* outb = mat ? vb : kb;
        float ac[8][4];
#pragma unroll
        for (int nf = 0; nf < 8; ++nf)
#pragma unroll
            for (int i = 0; i < 4; ++i) ac[nf][i] = 0.f;
#pragma unroll
        for (int ks = 0; ks < 4; ++ks) {
            uint32_t ah[4], bx[4];
            ldsm_x4(ah, Bbase + laneW + ks * 32);
#pragma unroll
            for (int nfp = 0; nfp < 4; ++nfp) {
                ldsm_x4(bx, sb + OFF_A2 + laneB2
                            + (uint32_t)((N0 + nfp * 16) * SKD * 2) + ks * 32);
                mma16816(ac[2 * nfp],     ah, bx[0], bx[1]);
                mma16816(ac[2 * nfp + 1], ah, bx[2], bx[3]);
            }
        }
#pragma unroll
        for (int nf = 0; nf < 8; ++nf) {
            int p = N0 + nf * 8 + 2 * tg;
            int e = M0 + g;
            stage[p * 64 + e]           = ac[nf][0];
            stage[(p + 1) * 64 + e]     = ac[nf][1];
            stage[p * 64 + e + 8]       = ac[nf][2];
            stage[(p + 1) * 64 + e + 8] = ac[nf][3];
        }
        __syncthreads();
#pragma unroll
        for (int j = 0; j < 16; ++j) {
            int idx = j * 256 + tid;
            float2 f = ((const float2*)stage)[idx];
            outb[idx] = pack2(f.x, f.y);
        }
        __syncthreads();
    }
}

// ===========================================================================
// attn_update (direct gmem k reads, static smem). grid (8,B), block 256
// ===========================================================================
__global__ void attn_update_kernel()
{
    __shared__ float qs[8][64];
    __shared__ float csw[8][8];
    __shared__ float attn_s[256][8];
    __shared__ float4 red[16][128];
    const int sp = blockIdx.x, b = blockIdx.y;
    const int tid = threadIdx.x;
    const int w = tid >> 5, lane = tid & 31;
    const int t = sp * 256 + tid;

    ((float*)qs)[tid]       = ((const float*)g_q4)[b * 512 + tid];
    ((float*)qs)[tid + 256] = ((const float*)g_q4)[b * 512 + tid + 256];
    __syncthreads();

    const uint4* kr = (const uint4*)(g_kb + ((size_t)b * 2048 + t) * 32);
    float a[8];
#pragma unroll
    for (int s = 0; s < 8; ++s) a[s] = 0.f;
#pragma unroll
    for (int i = 0; i < 8; ++i) {
        uint4 A = kr[i];
        float2 f0 = bf2f(A.x), f1 = bf2f(A.y), f2 = bf2f(A.z), f3 = bf2f(A.w);
#pragma unroll
        for (int s = 0; s < 8; ++s) {
            const float* q8 = &qs[s][8 * i];
            a[s] = fmaf(f0.x, q8[0], fmaf(f0.y, q8[1],
                   fmaf(f1.x, q8[2], fmaf(f1.y, q8[3],
                   fmaf(f2.x, q8[4], fmaf(f2.y, q8[5],
                   fmaf(f3.x, q8[6], fmaf(f3.y, q8[7], a[s]))))))));
        }
    }
    float mx = a[0];
#pragma unroll
    for (int s = 1; s < 8; ++s) mx = fmaxf(mx, a[s]);
    float sm = 0.f;
#pragma unroll
    for (int s = 0; s < 8; ++s) { a[s] = __expf(a[s] - mx); sm += a[s]; }
    float rv = 1.f / sm;
#pragma unroll
    for (int s = 0; s < 8; ++s) a[s] = a[s] * rv + 1e-8f;

    *(float4*)&attn_s[tid][0] = make_float4(a[0], a[1], a[2], a[3]);
    *(float4*)&attn_s[tid][4] = make_float4(a[4], a[5], a[6], a[7]);

#pragma unroll
    for (int s = 0; s < 8; ++s) {
        float v = a[s];
#pragma unroll
        for (int o = 16; o > 0; o >>= 1) v += __shfl_xor_sync(0xffffffffu, v, o);
        if (lane == 0) csw[w][s] = v;
    }
    __syncthreads();
    if (tid < 8) {
        float tt = 0.f;
#pragma unroll
        for (int ww = 0; ww < 8; ++ww) tt += csw[ww][tid];
        g_csP[sp * 1024 + b * 8 + tid] = tt;
    }

    const int dq = tid & 15, grp = tid >> 4;
    const uint2* V2 = (const uint2*)(g_vb + ((size_t)b * 2048 + sp * 256) * 32);
    float4 acc[8];
#pragma unroll
    for (int s = 0; s < 8; ++s) acc[s] = make_float4(0.f, 0.f, 0.f, 0.f);
#pragma unroll 4
    for (int j = 0; j < 16; ++j) {
        int tt = grp * 16 + j;
        uint2 vv = V2[tt * 16 + dq];
        float2 v01 = bf2f(vv.x), v23 = bf2f(vv.y);
        float4 A01 = *(const float4*)&attn_s[tt][0];
        float4 A23 = *(const float4*)&attn_s[tt][4];
        const float aw[8] = {A01.x, A01.y, A01.z, A01.w,
                             A23.x, A23.y, A23.z, A23.w};
#pragma unroll
        for (int s = 0; s < 8; ++s) {
            acc[s].x = fmaf(aw[s], v01.x, acc[s].x);
            acc[s].y = fmaf(aw[s], v01.y, acc[s].y);
            acc[s].z = fmaf(aw[s], v23.x, acc[s].z);
            acc[s].w = fmaf(aw[s], v23.y, acc[s].w);
        }
    }
#pragma unroll
    for (int s = 0; s < 8; ++s) red[grp][s * 16 + dq] = acc[s];
    __syncthreads();
    if (tid < 128) {
        float4 r = make_float4(0.f, 0.f, 0.f, 0.f);
#pragma unroll
        for (int q = 0; q < 16; ++q) {
            float4 tt = red[q][tid];
            r.x += tt.x; r.y += tt.y; r.z += tt.z; r.w += tt.w;
        }
        ((float4*)g_updp)[sp * 16384 + b * 128 + tid] = r;
    }
}

// ===========================================================================
// gru_mlp (grid 256, block 256, 4 slots/block) — coalesced transposed weights
// ===========================================================================
__global__ void gru_mlp_kernel(
    const float* __restrict__ bih, const float* __restrict__ bhh,
    const float* __restrict__ nm_w, const float* __restrict__ nm_b,
    const float* __restrict__ b1, const float* __restrict__ b2)
{
    const int blk = blockIdx.x;
    const int tid = threadIdx.x;
    const int ls = tid >> 6, d = tid & 63;
    const int bs = blk * 4 + ls;
    __shared__ float u[4][64], sp_s[4][64], h[4][64], hh[4][128], r4[4][4];

    float uacc = 0.f;
#pragma unroll
    for (int p = 0; p < 8; ++p) uacc += g_updp[p * 65536 + bs * 64 + d];
    float cs = 0.f;
#pragma unroll
    for (int p = 0; p < 8; ++p) cs += g_csP[p * 1024 + bs];
    u[ls][d]  = uacc / cs;
    sp_s[ls][d] = g_slots[bs * 64 + d];
    __syncthreads();

    float a0 = bih[d], a1 = bih[64 + d], a2 = bih[128 + d];
    float g0 = bhh[d], g1 = bhh[64 + d], g2 = bhh[128 + d];
#pragma unroll 8
    for (int c = 0; c < 64; ++c) {
        float uc = u[ls][c], sc = sp_s[ls][c];
        const float* wi = g_wihT + c * 192;
        const float* wh = g_whhT + c * 192;
        a0 = fmaf(uc, wi[d], a0);
        a1 = fmaf(uc, wi[64 + d], a1);
        a2 = fmaf(uc, wi[128 + d], a2);
        g0 = fmaf(sc, wh[d], g0);
        g1 = fmaf(sc, wh[64 + d], g1);
        g2 = fmaf(sc, wh[128 + d], g2);
    }
    float r = 1.f / (1.f + __expf(-(a0 + g0)));
    float z = 1.f / (1.f + __expf(-(a1 + g1)));
    float nn = tanhf(a2 + r * g2);
    float sl = (1.f - z) * nn + z * sp_s[ls][d];

    float su = sl, sq = sl * sl;
#pragma unroll
    for (int o = 16; o > 0; o >>= 1) {
        su += __shfl_xor_sync(0xffffffffu, su, o);
        sq += __shfl_xor_sync(0xffffffffu, sq, o);
    }
    if ((d & 31) == 0) { r4[ls][d >> 5] = su; r4[ls][2 + (d >> 5)] = sq; }
    __syncthreads();
    float ts = r4[ls][0] + r4[ls][1], tq = r4[ls][2] + r4[ls][3];
    float mu = ts * (1.f / 64.f);
    float inv = rsqrtf(tq * (1.f / 64.f) - mu * mu + 1e-5f);
    h[ls][d] = (sl - mu) * inv * nm_w[d] + nm_b[d];
    __syncthreads();

    float m0 = b1[d], m1 = b1[64 + d];
#pragma unroll 8
    for (int c = 0; c < 64; ++c) {
        float hc = h[ls][c];
        const float* w1r = g_w1T + c * 128;
        m0 = fmaf(hc, w1r[d], m0);
        m1 = fmaf(hc, w1r[64 + d], m1);
    }
    hh[ls][d] = fmaxf(m0, 0.f);
    hh[ls][64 + d] = fmaxf(m1, 0.f);
    __syncthreads();

    float o = b2[d];
#pragma unroll 8
    for (int j = 0; j < 128; ++j)
        o = fmaf(hh[ls][j], g_w2T[j * 64 + d], o);
    g_slots[bs * 64 + d] = sl + o;
}

// ===========================================================================
// Kernel 7: head
// ===========================================================================
__global__ void head_kernel(const float* __restrict__ head_w,
                            const float* __restrict__ head_b,
                            float* __restrict__ out)
{
    const int b = blockIdx.x;
    const int d = threadIdx.x;
    __shared__ float f[64];
    float a = 0.f;
#pragma unroll
    for (int s = 0; s < 8; ++s) a += g_slots[(b * 8 + s) * 64 + d];
    f[d] = a * 0.125f;
    __syncthreads();
    if (d < 15) {
        float o = head_b[d];
        const float* hw = head_w + d * 64;
#pragma unroll
        for (int c = 0; c < 64; ++c) o += f[c] * hw[c];
        out[b * 15 + d] = o;
    }
}

// ===========================================================================
extern "C" void kernel_launch(void* const* d_in, const int* in_sizes, int n_in,
                              void* d_out, int out_size)
{
    const float* x1      = (const float*)d_in[0];
    const float* x2      = (const float*)d_in[1];
    const float* conv1_w = (const float*)d_in[2];
    const float* conv1_b = (const float*)d_in[3];
    const float* conv2_w = (const float*)d_in[4];
    const float* conv2_b = (const float*)d_in[5];
    const float* norm_w  = (const float*)d_in[6];
    const float* norm_b  = (const float*)d_in[7];
    const float* ni_w    = (const float*)d_in[8];
    const float* ni_b    = (const float*)d_in[9];
    const float* ns_w    = (const float*)d_in[10];
    const float* ns_b    = (const float*)d_in[11];
    const float* nm_w    = (const float*)d_in[12];
    const float* nm_b    = (const float*)d_in[13];
    const float* slots_mu        = (const float*)d_in[14];
    const float* slots_log_sigma = (const float*)d_in[15];
    const float* Wq      = (const float*)d_in[16];
    const float* Wk      = (const float*)d_in[17];
    const float* Wv      = (const float*)d_in[18];
    const float* gru_wih = (const float*)d_in[19];
    const float* gru_whh = (const float*)d_in[20];
    const float* gru_bih = (const float*)d_in[21];
    const float* gru_bhh = (const float*)d_in[22];
    const float* mlp_w1  = (const float*)d_in[23];
    const float* mlp_b1  = (const float*)d_in[24];
    const float* mlp_w2  = (const float*)d_in[25];
    const float* mlp_b2  = (const float*)d_in[26];
    const float* head_w  = (const float*)d_in[27];
    const float* head_b  = (const float*)d_in[28];
    const float* noise   = (const float*)d_in[29];
    float* out = (float*)d_out;

    cudaFuncSetAttribute(conv_ln_kv_kernel,
                         cudaFuncAttributeMaxDynamicSharedMemorySize, SM_TOTAL);

    init_slots_kernel<<<256, 256>>>(slots_mu, slots_log_sigma, noise);    // 0
    wprep_kernel<<<240, 256>>>(conv1_w, conv2_w, Wk, Wv,                  // 1
                               gru_wih, gru_whh, mlp_w1, mlp_w2);
    slot_q_kernel<<<128, 512>>>(ns_w, ns_b, Wq);                          // 2
    dim3 g1(8, 2, 128);
    conv_ln_kv_kernel<<<g1, 256, SM_TOTAL>>>(x1, x2, conv1_b, conv2_b,    // 3
                                             norm_w, norm_b, ni_w, ni_b);

    for (int it = 0; it < 3; ++it) {
        attn_update_kernel<<<dim3(8, 128), 256>>>();
        gru_mlp_kernel<<<256, 256>>>(gru_bih, gru_bhh, nm_w, nm_b,
                                     mlp_b1, mlp_b2);
        if (it < 2) slot_q_kernel<<<128, 512>>>(ns_w, ns_b, Wq);
    }
    head_kernel<<<128, 64>>>(head_w, head_b, out);
}

// round 17
// speedup vs baseline: 1.0998x; 1.0199x over previous
#include <cuda_runtime.h>
#include <cuda_bf16.h>
#include <cstdint>
#include <math.h>

// ---------------- scratch ---------------------------------------------------
__device__ uint32_t g_kb[128u * 2048u * 32u];   // k bf16 [B][N][64]
__device__ uint32_t g_vb[128u * 2048u * 32u];   // v bf16
__device__ float4   g_q4[128u * 8u * 16u];      // q fp32 [B,S,64]
__device__ float    g_slots[128 * 8 * 64];
__device__ float    g_csP[8 * 128 * 8];
__device__ float    g_updp[8 * 128 * 8 * 64];
__device__ uint32_t g_cwb[2][8192];             // conv W bf16 [64][256]/2
__device__ uint32_t g_wkb[2048], g_wvb[2048];   // Wk/Wv bf16 [64][64]/2
__device__ float    g_wihT[12288];              // [c][192]
__device__ float    g_whhT[12288];              // [c][192]
__device__ float    g_w1T[8192];                // [c][128]
__device__ float    g_w2T[8192];                // [j][64]

// ---------------- helpers ---------------------------------------------------
__device__ __forceinline__ void mma16816(float* c, const uint32_t* a,
                                         uint32_t b0, uint32_t b1) {
    asm volatile(
        "mma.sync.aligned.m16n8k16.row.col.f32.bf16.bf16.f32 "
        "{%0,%1,%2,%3}, {%4,%5,%6,%7}, {%8,%9}, {%0,%1,%2,%3};"
        : "+f"(c[0]), "+f"(c[1]), "+f"(c[2]), "+f"(c[3])
        : "r"(a[0]), "r"(a[1]), "r"(a[2]), "r"(a[3]), "r"(b0), "r"(b1));
}
__device__ __forceinline__ void ldsm_x4(uint32_t* r, uint32_t addr) {
    asm volatile("ldmatrix.sync.aligned.m8n8.x4.shared.b16 {%0,%1,%2,%3}, [%4];"
                 : "=r"(r[0]), "=r"(r[1]), "=r"(r[2]), "=r"(r[3]) : "r"(addr));
}
__device__ __forceinline__ void ldsm_x4_t(uint32_t* r, uint32_t addr) {
    asm volatile("ldmatrix.sync.aligned.m8n8.x4.trans.shared.b16 {%0,%1,%2,%3}, [%4];"
                 : "=r"(r[0]), "=r"(r[1]), "=r"(r[2]), "=r"(r[3]) : "r"(addr));
}
__device__ __forceinline__ uint32_t smem_u32(const void* p) {
    uint32_t a;
    asm("{ .reg .u64 t; cvta.to.shared.u64 t, %1; cvt.u32.u64 %0, t; }"
        : "=r"(a) : "l"(p));
    return a;
}
__device__ __forceinline__ uint32_t pack2(float a, float b) {
    __nv_bfloat162 h;
    h.x = __float2bfloat16_rn(a);
    h.y = __float2bfloat16_rn(b);
    return *(uint32_t*)&h;
}
__device__ __forceinline__ float2 bf2f(uint32_t u) {
    return __bfloat1622float2(*(__nv_bfloat162*)&u);
}

// conv smem layout
#define SX 136
#define SKD 72
#define OFF_XB0  0u
#define OFF_XB1  17408u
#define OFF_WB0  34816u
#define OFF_WB1  44032u
#define OFF_WK   53248u
#define OFF_WV   62464u
#define SM_TOTAL 71680u
#define OFF_YS    0u
#define OFF_A2    34816u
#define OFF_STAGE 0u

// attn_update dynamic smem layout (red OVERLAYS ktile: 32768 <= 36864)
#define AU_KT    0u        // uint4[256*9] = 36864 B (k tile, then v tile, then red)
#define AU_QS    36864u    // float[512]  = 2048 B
#define AU_AT    38912u    // float[256*8] = 8192 B
#define AU_CSW   47104u    // float[64] = 256 B
#define AU_TOTAL 47360u

// ===========================================================================
// Kernel 0a: init slots
// ===========================================================================
__global__ void init_slots_kernel(const float* __restrict__ mu,
                                  const float* __restrict__ ls,
                                  const float* __restrict__ noise)
{
    int i = blockIdx.x * 256 + threadIdx.x;
    int d = i & 63;
    g_slots[i] = mu[d] + expf(ls[d]) * noise[i];
}

// ===========================================================================
// Kernel 0b: weight prep
// ===========================================================================
__global__ void wprep_kernel(const float* __restrict__ cw1,
                             const float* __restrict__ cw2,
                             const float* __restrict__ Wk,
                             const float* __restrict__ Wv,
                             const float* __restrict__ wih,
                             const float* __restrict__ whh,
                             const float* __restrict__ w1,
                             const float* __restrict__ w2)
{
    int i = blockIdx.x * 256 + threadIdx.x;
    if (i < 8192) {
        g_cwb[0][i] = pack2(cw1[2 * i], cw1[2 * i + 1]);
    } else if (i < 16384) {
        int j = i - 8192;
        g_cwb[1][j] = pack2(cw2[2 * j], cw2[2 * j + 1]);
    } else if (i < 18432) {
        int j = i - 16384;
        g_wkb[j] = pack2(Wk[2 * j], Wk[2 * j + 1]);
    } else if (i < 20480) {
        int j = i - 18432;
        g_wvb[j] = pack2(Wv[2 * j], Wv[2 * j + 1]);
    } else if (i < 32768) {
        int j = i - 20480;
        int c = j / 192, row = j % 192;
        g_wihT[j] = wih[row * 64 + c];
    } else if (i < 45056) {
        int j = i - 32768;
        int c = j / 192, row = j % 192;
        g_whhT[j] = whh[row * 64 + c];
    } else if (i < 53248) {
        int j = i - 45056;
        int c = j / 128, col = j % 128;
        g_w1T[j] = w1[col * 64 + c];
    } else if (i < 61440) {
        int j3 = i - 53248;
        int j = j3 / 64, d = j3 % 64;
        g_w2T[j3] = w2[d * 128 + j];
    }
}

// ===========================================================================
// Kernel slot_q: q = LN(slots, ns) @ Wq^T * scale. grid B, block 512
// ===========================================================================
__global__ void slot_q_kernel(const float* __restrict__ ns_w,
                              const float* __restrict__ ns_b,
                              const float* __restrict__ Wq)
{
    __shared__ float sn[8][64];
    __shared__ float Wqt[64][65];
    __shared__ float wsum[16], wsq[16];
    const int b = blockIdx.x;
    const int tid = threadIdx.x;
    const int s = tid >> 6, d = tid & 63;

#pragma unroll
    for (int j = 0; j < 8; ++j) {
        int lin = j * 512 + tid;
        int e = lin >> 6, c = lin & 63;
        Wqt[c][e] = Wq[lin];
    }
    float v = g_slots[(b * 8 + s) * 64 + d];
    float su = v, sq = v * v;
#pragma unroll
    for (int o = 16; o > 0; o >>= 1) {
        su += __shfl_xor_sync(0xffffffffu, su, o);
        sq += __shfl_xor_sync(0xffffffffu, sq, o);
    }
    if ((tid & 31) == 0) { wsum[tid >> 5] = su; wsq[tid >> 5] = sq; }
    __syncthreads();
    float ts = wsum[s * 2] + wsum[s * 2 + 1];
    float tq = wsq[s * 2] + wsq[s * 2 + 1];
    float mu = ts * (1.f / 64.f);
    float inv = rsqrtf(tq * (1.f / 64.f) - mu * mu + 1e-5f);
    sn[s][d] = (v - mu) * inv * ns_w[d] + ns_b[d];
    __syncthreads();
    float acc = 0.f;
#pragma unroll
    for (int c = 0; c < 64; ++c) acc += sn[s][c] * Wqt[c][d];
    ((float*)g_q4)[(b * 8 + s) * 64 + d] = acc * 0.125f;
}

// ===========================================================================
// Kernel 1 (profiled slot): conv (pipelined, double-buffered) -> LN -> LN
// -> k,v GEMMs. grid (8, 2, 128) block 256
// ===========================================================================
__global__ __launch_bounds__(256)
void conv_ln_kv_kernel(
    const float* __restrict__ x1, const float* __restrict__ x2,
    const float* __restrict__ cb1, const float* __restrict__ cb2,
    const float* __restrict__ norm_w, const float* __restrict__ norm_b,
    const float* __restrict__ ni_w,  const float* __restrict__ ni_b)
{
    extern __shared__ char smem[];
    const uint32_t sb = smem_u32(smem);
    const int tid = threadIdx.x;
    const int w = tid >> 5, lane = tid & 31;
    const int g = lane >> 2, tg = lane & 3;
    const int rowin = lane & 7, quad = lane >> 3;
    const int M0 = (w & 3) * 16;
    const int N0 = (w >> 2) * 64;
    const int b = blockIdx.z, src = blockIdx.y;
    const int p0 = blockIdx.x * 128;

    const float* X    = (src ? x2 : x1) + (size_t)b * 262144 + p0;
    const float* bias = src ? cb2 : cb1;
    const uint4* Wsrc = (const uint4*)(g_cwb[src]);

    const uint32_t laneW  = (uint32_t)(((M0 + rowin + (quad & 1) * 8) * SKD
                                        + (quad >> 1) * 8) * 2);
    const uint32_t laneBX = (uint32_t)(((rowin + (quad & 1) * 8) * SX
                                        + N0 + (quad >> 1) * 8) * 2);
    const uint32_t laneB2 = (uint32_t)(((rowin + (quad >> 1) * 8) * SKD
                                        + (quad & 1) * 8) * 2);

#pragma unroll
    for (int it = 0; it < 2; ++it) {
        int idx = it * 256 + tid;
        int e = idx >> 3, q = idx & 7;
        *(uint4*)(smem + OFF_WK + (uint32_t)(e * 144 + q * 16)) =
            ((const uint4*)g_wkb)[e * 8 + q];
        *(uint4*)(smem + OFF_WV + (uint32_t)(e * 144 + q * 16)) =
            ((const uint4*)g_wvb)[e * 8 + q];
    }

    // prologue: chunk 0 -> buf0
#pragma unroll
    for (int it = 0; it < 8; ++it) {
        int idx = it * 256 + tid;
        int ch = idx >> 5, p4 = idx & 31;
        float4 x4 = *(const float4*)(X + (size_t)ch * 1024 + p4 * 4);
        uint2 pr;
        pr.x = pack2(x4.x, x4.y);
        pr.y = pack2(x4.z, x4.w);
        *(uint2*)(smem + OFF_XB0 + (uint32_t)((ch * SX + p4 * 4) * 2)) = pr;
    }
#pragma unroll
    for (int it = 0; it < 2; ++it) {
        int idx = it * 256 + tid;
        int d = idx >> 3, q = idx & 7;
        *(uint4*)(smem + OFF_WB0 + (uint32_t)(d * 144 + q * 16)) =
            Wsrc[d * 32 + q];
    }
    __syncthreads();

    float acc[8][4];
#pragma unroll
    for (int nf = 0; nf < 8; ++nf)
#pragma unroll
        for (int i = 0; i < 4; ++i) acc[nf][i] = 0.f;

    const uint32_t xoff[2] = {OFF_XB0, OFF_XB1};
    const uint32_t woff[2] = {OFF_WB0, OFF_WB1};

#pragma unroll
    for (int chunk = 0; chunk < 4; ++chunk) {
        const int cur = chunk & 1;
        float4 xv[8];
        uint4 wv[2];
        if (chunk < 3) {
            const int cb = (chunk + 1) * 64;
#pragma unroll
            for (int it = 0; it < 8; ++it) {
                int idx = it * 256 + tid;
                int ch = idx >> 5, p4 = idx & 31;
                xv[it] = *(const float4*)(X + (size_t)(cb + ch) * 1024 + p4 * 4);
            }
#pragma unroll
            for (int it = 0; it < 2; ++it) {
                int idx = it * 256 + tid;
                int d = idx >> 3, q = idx & 7;
                wv[it] = Wsrc[d * 32 + (chunk + 1) * 8 + q];
            }
        }
        const uint32_t xb = sb + xoff[cur];
        const uint32_t wb = sb + woff[cur];
#pragma unroll
        for (int ks = 0; ks < 4; ++ks) {
            uint32_t ah[4], bx[4];
            ldsm_x4(ah, wb + laneW + ks * 32);
#pragma unroll
            for (int nfp = 0; nfp < 4; ++nfp) {
                ldsm_x4_t(bx, xb + laneBX
                              + (uint32_t)(ks * 16 * SX * 2) + nfp * 32);
                mma16816(acc[2 * nfp],     ah, bx[0], bx[1]);
                mma16816(acc[2 * nfp + 1], ah, bx[2], bx[3]);
            }
        }
        if (chunk < 3) {
            const int nxt = cur ^ 1;
#pragma unroll
            for (int it = 0; it < 8; ++it) {
                int idx = it * 256 + tid;
                int ch = idx >> 5, p4 = idx & 31;
                uint2 pr;
                pr.x = pack2(xv[it].x, xv[it].y);
                pr.y = pack2(xv[it].z, xv[it].w);
                *(uint2*)(smem + xoff[nxt] +
                          (uint32_t)((ch * SX + p4 * 4) * 2)) = pr;
            }
#pragma unroll
            for (int it = 0; it < 2; ++it) {
                int idx = it * 256 + tid;
                int d = idx >> 3, q = idx & 7;
                *(uint4*)(smem + woff[nxt] + (uint32_t)(d * 144 + q * 16)) =
                    wv[it];
            }
        }
        __syncthreads();
    }

    float* Ys = (float*)(smem + OFF_YS);
    {
        float b0 = bias[M0 + g], b8 = bias[M0 + g + 8];
#pragma unroll
        for (int nf = 0; nf < 8; ++nf) {
            int p = N0 + nf * 8 + 2 * tg;
            Ys[p * 65 + M0 + g]           = acc[nf][0] + b0;
            Ys[(p + 1) * 65 + M0 + g]     = acc[nf][1] + b0;
            Ys[p * 65 + M0 + g + 8]       = acc[nf][2] + b8;
            Ys[(p + 1) * 65 + M0 + g + 8] = acc[nf][3] + b8;
        }
    }
    __syncthreads();

    if (tid < 128) {
        float* row = Ys + tid * 65;
        float s = 0.f, q = 0.f;
#pragma unroll
        for (int d = 0; d < 64; ++d) { float v = row[d]; s += v; q += v * v; }
        float mu = s * (1.f / 64.f);
        float inv = rsqrtf(q * (1.f / 64.f) - mu * mu + 1e-5f);
        s = 0.f; q = 0.f;
#pragma unroll
        for (int d = 0; d < 64; ++d) {
            float y = (row[d] - mu) * inv * norm_w[d] + norm_b[d];
            row[d] = y; s += y; q += y * y;
        }
        mu = s * (1.f / 64.f);
        inv = rsqrtf(q * (1.f / 64.f) - mu * mu + 1e-5f);
#pragma unroll
        for (int d = 0; d < 64; ++d)
            row[d] = (row[d] - mu) * inv * ni_w[d] + ni_b[d];
    }
    __syncthreads();

#pragma unroll
    for (int it = 0; it < 16; ++it) {
        int idx = it * 256 + tid;
        int p = idx >> 5, d2 = idx & 31;
        *(uint32_t*)(smem + OFF_A2 + (uint32_t)((p * SKD + 2 * d2) * 2)) =
            pack2(Ys[p * 65 + 2 * d2], Ys[p * 65 + 2 * d2 + 1]);
    }
    __syncthreads();

    uint32_t* kb = g_kb + (size_t)(b * 2048 + src * 1024 + p0) * 32;
    uint32_t* vb = g_vb + (size_t)(b * 2048 + src * 1024 + p0) * 32;
    float* stage = (float*)(smem + OFF_STAGE);

#pragma unroll
    for (int mat = 0; mat < 2; ++mat) {
        uint32_t Bbase = sb + (mat ? OFF_WV : OFF_WK);
        uint32_t* outb = mat ? vb : kb;
        float ac[8][4];
#pragma unroll
        for (int nf = 0; nf < 8; ++nf)
#pragma unroll
            for (int i = 0; i < 4; ++i) ac[nf][i] = 0.f;
#pragma unroll
        for (int ks = 0; ks < 4; ++ks) {
            uint32_t ah[4], bx[4];
            ldsm_x4(ah, Bbase + laneW + ks * 32);
#pragma unroll
            for (int nfp = 0; nfp < 4; ++nfp) {
                ldsm_x4(bx, sb + OFF_A2 + laneB2
                            + (uint32_t)((N0 + nfp * 16) * SKD * 2) + ks * 32);
                mma16816(ac[2 * nfp],     ah, bx[0], bx[1]);
                mma16816(ac[2 * nfp + 1], ah, bx[2], bx[3]);
            }
        }
#pragma unroll
        for (int nf = 0; nf < 8; ++nf) {
            int p = N0 + nf * 8 + 2 * tg;
            int e = M0 + g;
            stage[p * 64 + e]           = ac[nf][0];
            stage[(p + 1) * 64 + e]     = ac[nf][1];
            stage[p * 64 + e + 8]       = ac[nf][2];
            stage[(p + 1) * 64 + e + 8] = ac[nf][3];
        }
        __syncthreads();
#pragma unroll
        for (int j = 0; j < 16; ++j) {
            int idx = j * 256 + tid;
            float2 f = ((const float2*)stage)[idx];
            outb[idx] = pack2(f.x, f.y);
        }
        __syncthreads();
    }
}

// ===========================================================================
// attn_update: smem-staged k/v (coalesced gmem loads); red overlays tile.
// grid (8, B), block 256, dynamic smem AU_TOTAL.
// ===========================================================================
__global__ void attn_update_kernel()
{
    extern __shared__ char dsm[];
    uint4* ktile  = (uint4*)(dsm + AU_KT);     // [256 tokens][9] (stride 144B)
    float* qs     = (float*)(dsm + AU_QS);     // [8][64]
    float* attn_s = (float*)(dsm + AU_AT);     // [256][8]
    float4* red   = (float4*)(dsm + AU_KT);    // OVERLAY (32768 <= 36864)
    float* csw    = (float*)(dsm + AU_CSW);    // [8][8]
    const int sp = blockIdx.x, b = blockIdx.y;
    const int tid = threadIdx.x;
    const int w = tid >> 5, lane = tid & 31;

    qs[tid]       = ((const float*)g_q4)[b * 512 + tid];
    qs[tid + 256] = ((const float*)g_q4)[b * 512 + tid + 256];

    // ---- coalesced k tile load (256 tokens x 8 uint4) ---------------------
    const uint4* ksrc = (const uint4*)(g_kb + ((size_t)b * 2048 + sp * 256) * 32);
#pragma unroll
    for (int j = 0; j < 8; ++j) {
        int idx = j * 256 + tid;
        ktile[(idx >> 3) * 9 + (idx & 7)] = ksrc[idx];
    }
    __syncthreads();

    // ---- phase 1: logits + softmax for token tid --------------------------
    float a[8];
#pragma unroll
    for (int s = 0; s < 8; ++s) a[s] = 0.f;
#pragma unroll
    for (int i = 0; i < 8; ++i) {
        uint4 A = ktile[tid * 9 + i];
        float2 f0 = bf2f(A.x), f1 = bf2f(A.y), f2 = bf2f(A.z), f3 = bf2f(A.w);
#pragma unroll
        for (int s = 0; s < 8; ++s) {
            const float* q8 = qs + s * 64 + 8 * i;
            a[s] = fmaf(f0.x, q8[0], fmaf(f0.y, q8[1],
                   fmaf(f1.x, q8[2], fmaf(f1.y, q8[3],
                   fmaf(f2.x, q8[4], fmaf(f2.y, q8[5],
                   fmaf(f3.x, q8[6], fmaf(f3.y, q8[7], a[s]))))))));
        }
    }
    float mx = a[0];
#pragma unroll
    for (int s = 1; s < 8; ++s) mx = fmaxf(mx, a[s]);
    float sm = 0.f;
#pragma unroll
    for (int s = 0; s < 8; ++s) { a[s] = __expf(a[s] - mx); sm += a[s]; }
    float rv = 1.f / sm;
#pragma unroll
    for (int s = 0; s < 8; ++s) a[s] = a[s] * rv + 1e-8f;

    *(float4*)&attn_s[tid * 8]     = make_float4(a[0], a[1], a[2], a[3]);
    *(float4*)&attn_s[tid * 8 + 4] = make_float4(a[4], a[5], a[6], a[7]);

#pragma unroll
    for (int s = 0; s < 8; ++s) {
        float v = a[s];
#pragma unroll
        for (int o = 16; o > 0; o >>= 1) v += __shfl_xor_sync(0xffffffffu, v, o);
        if (lane == 0) csw[w * 8 + s] = v;
    }
    __syncthreads();
    if (tid < 8) {
        float tt = 0.f;
#pragma unroll
        for (int ww = 0; ww < 8; ++ww) tt += csw[ww * 8 + tid];
        g_csP[sp * 1024 + b * 8 + tid] = tt;
    }

    // ---- coalesced v tile load (reuses ktile buffer) ----------------------
    const uint4* vsrc = (const uint4*)(g_vb + ((size_t)b * 2048 + sp * 256) * 32);
#pragma unroll
    for (int j = 0; j < 8; ++j) {
        int idx = j * 256 + tid;
        ktile[(idx >> 3) * 9 + (idx & 7)] = vsrc[idx];
    }
    __syncthreads();

    // ---- phase 2: updates partial -----------------------------------------
    const int dq = tid & 15, grp = tid >> 4;
    const uint2* vt = (const uint2*)(dsm + AU_KT); // token stride = 18 uint2
    float4 acc[8];
#pragma unroll
    for (int s = 0; s < 8; ++s) acc[s] = make_float4(0.f, 0.f, 0.f, 0.f);
#pragma unroll 4
    for (int j = 0; j < 16; ++j) {
        int t = grp * 16 + j;
        uint2 vv = vt[t * 18 + dq];
        float2 v01 = bf2f(vv.x), v23 = bf2f(vv.y);
        float4 A01 = *(const float4*)&attn_s[t * 8];
        float4 A23 = *(const float4*)&attn_s[t * 8 + 4];
        const float aw[8] = {A01.x, A01.y, A01.z, A01.w,
                             A23.x, A23.y, A23.z, A23.w};
#pragma unroll
        for (int s = 0; s < 8; ++s) {
            acc[s].x = fmaf(aw[s], v01.x, acc[s].x);
            acc[s].y = fmaf(aw[s], v01.y, acc[s].y);
            acc[s].z = fmaf(aw[s], v23.x, acc[s].z);
            acc[s].w = fmaf(aw[s], v23.y, acc[s].w);
        }
    }
    __syncthreads();               // all v reads done; red may overwrite tile
#pragma unroll
    for (int s = 0; s < 8; ++s) red[grp * 128 + s * 16 + dq] = acc[s];
    __syncthreads();
    if (tid < 128) {
        float4 r = make_float4(0.f, 0.f, 0.f, 0.f);
#pragma unroll
        for (int q = 0; q < 16; ++q) {
            float4 tt = red[q * 128 + tid];
            r.x += tt.x; r.y += tt.y; r.z += tt.z; r.w += tt.w;
        }
        ((float4*)g_updp)[sp * 16384 + b * 128 + tid] = r;
    }
}

// ===========================================================================
// gru_mlp (grid 256, block 256, 4 slots/block) — coalesced transposed weights
// ===========================================================================
__global__ void gru_mlp_kernel(
    const float* __restrict__ bih, const float* __restrict__ bhh,
    const float* __restrict__ nm_w, const float* __restrict__ nm_b,
    const float* __restrict__ b1, const float* __restrict__ b2)
{
    const int blk = blockIdx.x;
    const int tid = threadIdx.x;
    const int ls = tid >> 6, d = tid & 63;
    const int bs = blk * 4 + ls;
    __shared__ float u[4][64], sp_s[4][64], h[4][64], hh[4][128], r4[4][4];

    float uacc = 0.f;
#pragma unroll
    for (int p = 0; p < 8; ++p) uacc += g_updp[p * 65536 + bs * 64 + d];
    float cs = 0.f;
#pragma unroll
    for (int p = 0; p < 8; ++p) cs += g_csP[p * 1024 + bs];
    u[ls][d]  = uacc / cs;
    sp_s[ls][d] = g_slots[bs * 64 + d];
    __syncthreads();

    float a0 = bih[d], a1 = bih[64 + d], a2 = bih[128 + d];
    float g0 = bhh[d], g1 = bhh[64 + d], g2 = bhh[128 + d];
#pragma unroll 8
    for (int c = 0; c < 64; ++c) {
        float uc = u[ls][c], sc = sp_s[ls][c];
        const float* wi = g_wihT + c * 192;
        const float* wh = g_whhT + c * 192;
        a0 = fmaf(uc, wi[d], a0);
        a1 = fmaf(uc, wi[64 + d], a1);
        a2 = fmaf(uc, wi[128 + d], a2);
        g0 = fmaf(sc, wh[d], g0);
        g1 = fmaf(sc, wh[64 + d], g1);
        g2 = fmaf(sc, wh[128 + d], g2);
    }
    float r = 1.f / (1.f + __expf(-(a0 + g0)));
    float z = 1.f / (1.f + __expf(-(a1 + g1)));
    float nn = tanhf(a2 + r * g2);
    float sl = (1.f - z) * nn + z * sp_s[ls][d];

    float su = sl, sq = sl * sl;
#pragma unroll
    for (int o = 16; o > 0; o >>= 1) {
        su += __shfl_xor_sync(0xffffffffu, su, o);
        sq += __shfl_xor_sync(0xffffffffu, sq, o);
    }
    if ((d & 31) == 0) { r4[ls][d >> 5] = su; r4[ls][2 + (d >> 5)] = sq; }
    __syncthreads();
    float ts = r4[ls][0] + r4[ls][1], tq = r4[ls][2] + r4[ls][3];
    float mu = ts * (1.f / 64.f);
    float inv = rsqrtf(tq * (1.f / 64.f) - mu * mu + 1e-5f);
    h[ls][d] = (sl - mu) * inv * nm_w[d] + nm_b[d];
    __syncthreads();

    float m0 = b1[d], m1 = b1[64 + d];
#pragma unroll 8
    for (int c = 0; c < 64; ++c) {
        float hc = h[ls][c];
        const float* w1r = g_w1T + c * 128;
        m0 = fmaf(hc, w1r[d], m0);
        m1 = fmaf(hc, w1r[64 + d], m1);
    }
    hh[ls][d] = fmaxf(m0, 0.f);
    hh[ls][64 + d] = fmaxf(m1, 0.f);
    __syncthreads();

    float o = b2[d];
#pragma unroll 8
    for (int j = 0; j < 128; ++j)
        o = fmaf(hh[ls][j], g_w2T[j * 64 + d], o);
    g_slots[bs * 64 + d] = sl + o;
}

// ===========================================================================
// Kernel 7: head
// ===========================================================================
__global__ void head_kernel(const float* __restrict__ head_w,
                            const float* __restrict__ head_b,
                            float* __restrict__ out)
{
    const int b = blockIdx.x;
    const int d = threadIdx.x;
    __shared__ float f[64];
    float a = 0.f;
#pragma unroll
    for (int s = 0; s < 8; ++s) a += g_slots[(b * 8 + s) * 64 + d];
    f[d] = a * 0.125f;
    __syncthreads();
    if (d < 15) {
        float o = head_b[d];
        const float* hw = head_w + d * 64;
#pragma unroll
        for (int c = 0; c < 64; ++c) o += f[c] * hw[c];
        out[b * 15 + d] = o;
    }
}

// ===========================================================================
extern "C" void kernel_launch(void* const* d_in, const int* in_sizes, int n_in,
                              void* d_out, int out_size)
{
    const float* x1      = (const float*)d_in[0];
    const float* x2      = (const float*)d_in[1];
    const float* conv1_w = (const float*)d_in[2];
    const float* conv1_b = (const float*)d_in[3];
    const float* conv2_w = (const float*)d_in[4];
    const float* conv2_b = (const float*)d_in[5];
    const float* norm_w  = (const float*)d_in[6];
    const float* norm_b  = (const float*)d_in[7];
    const float* ni_w    = (const float*)d_in[8];
    const float* ni_b    = (const float*)d_in[9];
    const float* ns_w    = (const float*)d_in[10];
    const float* ns_b    = (const float*)d_in[11];
    const float* nm_w    = (const float*)d_in[12];
    const float* nm_b    = (const float*)d_in[13];
    const float* slots_mu        = (const float*)d_in[14];
    const float* slots_log_sigma = (const float*)d_in[15];
    const float* Wq      = (const float*)d_in[16];
    const float* Wk      = (const float*)d_in[17];
    const float* Wv      = (const float*)d_in[18];
    const float* gru_wih = (const float*)d_in[19];
    const float* gru_whh = (const float*)d_in[20];
    const float* gru_bih = (const float*)d_in[21];
    const float* gru_bhh = (const float*)d_in[22];
    const float* mlp_w1  = (const float*)d_in[23];
    const float* mlp_b1  = (const float*)d_in[24];
    const float* mlp_w2  = (const float*)d_in[25];
    const float* mlp_b2  = (const float*)d_in[26];
    const float* head_w  = (const float*)d_in[27];
    const float* head_b  = (const float*)d_in[28];
    const float* noise   = (const float*)d_in[29];
    float* out = (float*)d_out;

    cudaFuncSetAttribute(conv_ln_kv_kernel,
                         cudaFuncAttributeMaxDynamicSharedMemorySize, SM_TOTAL);
    cudaFuncSetAttribute(attn_update_kernel,
                         cudaFuncAttributeMaxDynamicSharedMemorySize, AU_TOTAL);

    init_slots_kernel<<<256, 256>>>(slots_mu, slots_log_sigma, noise);    // 0
    wprep_kernel<<<240, 256>>>(conv1_w, conv2_w, Wk, Wv,                  // 1
                               gru_wih, gru_whh, mlp_w1, mlp_w2);
    slot_q_kernel<<<128, 512>>>(ns_w, ns_b, Wq);                          // 2
    dim3 g1(8, 2, 128);
    conv_ln_kv_kernel<<<g1, 256, SM_TOTAL>>>(x1, x2, conv1_b, conv2_b,    // 3
                                             norm_w, norm_b, ni_w, ni_b);

    for (int it = 0; it < 3; ++it) {
        attn_update_kernel<<<dim3(8, 128), 256, AU_TOTAL>>>();
        gru_mlp_kernel<<<256, 256>>>(gru_bih, gru_bhh, nm_w, nm_b,
                                     mlp_b1, mlp_b2);
        if (it < 2) slot_q_kernel<<<128, 512>>>(ns_w, ns_b, Wq);
    }
    head_kernel<<<128, 64>>>(head_w, head_b, out);
}